// round 1
// baseline (speedup 1.0000x reference)
#include <cuda_runtime.h>
#include <math.h>

#define TWO_PI_F 6.2831853071795864769f

// ---------------- scratch (static __device__ allowed) ----------------
__device__ float g_nodes[4096 * 6];
__device__ float g_label[4096];
__device__ float g_efeat[16128 * 10];
__device__ int   g_slot[4096 * 16];
__device__ int   g_cnt[4096];

__device__ __forceinline__ float frelu(float x) { return x > 0.f ? x : 0.f; }
__device__ __forceinline__ float dround(float x) {
    return x - sinf(x * TWO_PI_F) * (1.0f / TWO_PI_F);
}

// ---------------- kernel 0: zero edge-bucket counters ----------------
__global__ void zero_cnt_kernel() {
    int i = blockIdx.x * 256 + threadIdx.x;
    if (i < 4096) g_cnt[i] = 0;
}

// ---------------- kernel 1: patches + conv1 + conv2 + dense1 ----------------
// grid = 4096 (one patch/node per block), block = 128 threads
// dynamic smem layout (floats):
//   w2_s   [14400]  conv2 weights (tap*1600 + ci*40 + co)
//   act1_s [10240]  conv1 output, channel-planar [40][256]; reused as act2 [256][40]
//   tok_s  [324]    18x18 zero-padded token tile
//   w1_s   [360]    conv1 weights
//   b1_s   [40], b2_s [40]
//   red_s  [64]     reductions
#define K1_SMEM_FLOATS (14400 + 10240 + 324 + 360 + 40 + 40 + 64)

__global__ void __launch_bounds__(128) patch_kernel(
    const float* __restrict__ img, const float* __restrict__ lab,
    const float* __restrict__ msk,
    const float* __restrict__ w1, const float* __restrict__ b1,
    const float* __restrict__ w2, const float* __restrict__ b2,
    const float* __restrict__ d1w, const float* __restrict__ d1b)
{
    extern __shared__ float smem[];
    float* w2_s   = smem;
    float* act1_s = w2_s + 14400;
    float* tok_s  = act1_s + 10240;
    float* w1_s   = tok_s + 324;
    float* b1_s   = w1_s + 360;
    float* b2_s   = b1_s + 40;
    float* red_s  = b2_s + 40;

    const int t = threadIdx.x;
    const int n = blockIdx.x;
    const int g = n >> 10;
    const int ij = n & 1023;
    const int i = ij >> 5, j = ij & 31;
    const int sx = g & 1, sy = g >> 1;            // SHIFTS order (0,0)(1,0)(0,1)(1,1)
    const int r0 = 16 * i + 8 * sx - 4;
    const int c0 = 16 * j + 8 * sy - 4;
    const float cid = (float)((2 * i + sx) * 64 + (2 * j + sy));

    // stage weights
    for (int k = t; k < 3600; k += 128) ((float4*)w2_s)[k] = ((const float4*)w2)[k];
    for (int k = t; k < 360; k += 128) w1_s[k] = w1[k];
    if (t < 40) { b1_s[t] = b1[t]; b2_s[t] = b2[t]; }
    for (int k = t; k < 324; k += 128) tok_s[k] = 0.f;
    __syncthreads();

    // tokens (mask-filtered image) + label sums
    float sum_f = 0.f, sum_lp = 0.f;
    #pragma unroll
    for (int pp = 0; pp < 2; ++pp) {
        int p = t + 128 * pp;
        int py = p >> 4, px = p & 15;
        int gr = r0 + py, gc = c0 + px;
        bool inb = (gr >= 0 && gr < 512 && gc >= 0 && gc < 512);
        float m = inb ? msk[gr * 512 + gc] : -1.f;
        float f = (m == cid) ? 1.f : 0.f;
        float iv = (inb ? img[gr * 512 + gc] : 0.f) * f;
        float lv = (inb ? lab[gr * 512 + gc] : 0.f) * f;
        tok_s[(py + 1) * 18 + px + 1] = iv;
        sum_f += f; sum_lp += lv;
    }
    #pragma unroll
    for (int o = 16; o; o >>= 1) {
        sum_f  += __shfl_down_sync(0xffffffffu, sum_f, o);
        sum_lp += __shfl_down_sync(0xffffffffu, sum_lp, o);
    }
    if ((t & 31) == 0) { red_s[(t >> 5) * 2] = sum_f; red_s[(t >> 5) * 2 + 1] = sum_lp; }
    __syncthreads();
    if (t == 0) {
        float sf = red_s[0] + red_s[2] + red_s[4] + red_s[6];
        float sl = red_s[1] + red_s[3] + red_s[5] + red_s[7];
        g_label[n] = dround(dround(sl / (sf + 1e-8f)));
    }

    // ---- conv1: 1 -> 40, 3x3 SAME, relu; store channel-planar [c][p] ----
    #pragma unroll
    for (int pp = 0; pp < 2; ++pp) {
        int p = t + 128 * pp;
        int py = p >> 4, px = p & 15;
        float t9[9];
        #pragma unroll
        for (int k = 0; k < 9; k++) t9[k] = tok_s[(py + k / 3) * 18 + px + (k % 3)];
        #pragma unroll 8
        for (int c = 0; c < 40; c++) {
            float s = b1_s[c];
            #pragma unroll
            for (int k = 0; k < 9; k++) s = fmaf(t9[k], w1_s[k * 40 + c], s);
            act1_s[c * 256 + p] = frelu(s);
        }
    }
    __syncthreads();

    // ---- conv2: register-tiled, f32x2 packed FMA ----
    // warp w owns cos [10w, 10w+10); lane l owns pixels {32j + l}
    const int w  = t >> 5, l = t & 31;
    const int px = l & 15, py0 = l >> 4;

    unsigned long long acc[8][5];
    #pragma unroll
    for (int jj = 0; jj < 8; jj++)
        #pragma unroll
        for (int q = 0; q < 5; q++) acc[jj][q] = 0ull;

    #pragma unroll
    for (int tap = 0; tap < 9; ++tap) {
        const int dy = tap / 3 - 1, dx = tap % 3 - 1;
        const int xx = px + dx;
        const bool vx = ((unsigned)xx < 16u);
        int base[8]; bool vld[8];
        #pragma unroll
        for (int jj = 0; jj < 8; jj++) {
            int yy = 2 * jj + py0 + dy;
            vld[jj] = vx && ((unsigned)yy < 16u);
            base[jj] = yy * 16 + xx;
        }
        const float* wp = w2_s + tap * 1600 + 10 * w;
        const float* ap = act1_s;
        #pragma unroll 2
        for (int ci = 0; ci < 40; ++ci) {
            unsigned long long wv[5];
            #pragma unroll
            for (int q = 0; q < 5; q++)
                wv[q] = *(const unsigned long long*)(wp + 2 * q);
            #pragma unroll
            for (int jj = 0; jj < 8; jj++) {
                float a = vld[jj] ? ap[base[jj]] : 0.f;
                unsigned long long a2;
                asm("mov.b64 %0, {%1, %2};" : "=l"(a2) : "f"(a), "f"(a));
                #pragma unroll
                for (int q = 0; q < 5; q++)
                    asm("fma.rn.f32x2 %0, %1, %2, %0;"
                        : "+l"(acc[jj][q]) : "l"(a2), "l"(wv[q]));
            }
            wp += 40; ap += 256;
        }
    }
    __syncthreads();   // all reads of act1 planes done

    // act2 = relu(acc + b2) stored flat [p*40 + co] (reuse act1_s)
    #pragma unroll
    for (int jj = 0; jj < 8; jj++) {
        int p = 32 * jj + l;
        #pragma unroll
        for (int q = 0; q < 5; q++) {
            float lo, hi;
            asm("mov.b64 {%0, %1}, %2;" : "=f"(lo), "=f"(hi) : "l"(acc[jj][q]));
            int co = 10 * w + 2 * q;
            float2 v = make_float2(frelu(lo + b2_s[co]), frelu(hi + b2_s[co + 1]));
            *(float2*)(act1_s + p * 40 + co) = v;
        }
    }
    __syncthreads();

    // ---- dense1: 10240 -> 6 cooperative GEMV ----
    float part[6] = {0.f, 0.f, 0.f, 0.f, 0.f, 0.f};
    for (int m = 0; m < 80; ++m) {
        int idx = t + 128 * m;
        float v = act1_s[idx];
        const float* wr = d1w + idx * 6;
        #pragma unroll
        for (int k = 0; k < 6; k++) part[k] = fmaf(v, __ldg(wr + k), part[k]);
    }
    #pragma unroll
    for (int k = 0; k < 6; k++)
        #pragma unroll
        for (int o = 16; o; o >>= 1) part[k] += __shfl_down_sync(0xffffffffu, part[k], o);
    if (l == 0) {
        #pragma unroll
        for (int k = 0; k < 6; k++) red_s[w * 6 + k] = part[k];
    }
    __syncthreads();
    if (t < 6) {
        float s = red_s[t] + red_s[6 + t] + red_s[12 + t] + red_s[18 + t];
        g_nodes[n * 6 + t] = frelu(s + d1b[t]);
    }
}

// ---------------- kernel 2: edge MLP + deterministic bucketing ----------------
__global__ void __launch_bounds__(128) edge_kernel(
    const int* __restrict__ snd, const int* __restrict__ rcv, int E,
    const float* __restrict__ we0, const float* __restrict__ be0,
    const float* __restrict__ we1, const float* __restrict__ be1,
    const float* __restrict__ we2, const float* __restrict__ be2,
    const float* __restrict__ we3, const float* __restrict__ be3)
{
    int e = blockIdx.x * 128 + threadIdx.x;
    if (e >= E) return;
    int s = snd[e], r = rcv[e];
    float x[13];
    #pragma unroll
    for (int k = 0; k < 6; k++) { x[k] = g_nodes[s * 6 + k]; x[6 + k] = g_nodes[r * 6 + k]; }
    x[12] = 1.f;

    float h0[5], h1[5], h2[5];
    #pragma unroll
    for (int k = 0; k < 5; k++) {
        float a = __ldg(be0 + k);
        #pragma unroll
        for (int i2 = 0; i2 < 13; i2++) a = fmaf(x[i2], __ldg(we0 + i2 * 5 + k), a);
        h0[k] = frelu(a);
    }
    #pragma unroll
    for (int k = 0; k < 5; k++) {
        float a = __ldg(be1 + k);
        #pragma unroll
        for (int i2 = 0; i2 < 5; i2++) a = fmaf(h0[i2], __ldg(we1 + i2 * 5 + k), a);
        h1[k] = frelu(a);
    }
    #pragma unroll
    for (int k = 0; k < 5; k++) {
        float a = __ldg(be2 + k);
        #pragma unroll
        for (int i2 = 0; i2 < 5; i2++) a = fmaf(h1[i2], __ldg(we2 + i2 * 5 + k), a);
        h2[k] = frelu(a);
    }
    #pragma unroll
    for (int k = 0; k < 10; k++) {
        float a = __ldg(be3 + k);
        #pragma unroll
        for (int i2 = 0; i2 < 5; i2++) a = fmaf(h2[i2], __ldg(we3 + i2 * 10 + k), a);
        g_efeat[e * 10 + k] = a;
    }
    int pos = atomicAdd(&g_cnt[r], 1);
    if (pos < 16) g_slot[r * 16 + pos] = e;
}

// ---------------- kernel 3: deterministic agg + node MLP + CE loss ----------------
__global__ void __launch_bounds__(128) node_kernel(
    const float* __restrict__ wn0, const float* __restrict__ bn0,
    const float* __restrict__ wn1, const float* __restrict__ bn1,
    const float* __restrict__ wn2, const float* __restrict__ bn2,
    const float* __restrict__ wn3, const float* __restrict__ bn3,
    const float* __restrict__ wout, const float* __restrict__ bout,
    float* __restrict__ out)
{
    int n = blockIdx.x * 128 + threadIdx.x;
    if (n >= 4096) return;

    int d = g_cnt[n]; if (d > 16) d = 16;
    int ids[16];
    for (int a = 0; a < d; a++) ids[a] = g_slot[n * 16 + a];
    // insertion sort by edge id -> deterministic summation order
    for (int a = 1; a < d; a++) {
        int key = ids[a]; int b = a - 1;
        while (b >= 0 && ids[b] > key) { ids[b + 1] = ids[b]; b--; }
        ids[b + 1] = key;
    }
    float agg[10];
    #pragma unroll
    for (int k = 0; k < 10; k++) agg[k] = 0.f;
    for (int a = 0; a < d; a++) {
        int e = ids[a];
        #pragma unroll
        for (int k = 0; k < 10; k++) agg[k] += g_efeat[e * 10 + k];
    }

    float x[17];
    #pragma unroll
    for (int k = 0; k < 6; k++) x[k] = g_nodes[n * 6 + k];
    #pragma unroll
    for (int k = 0; k < 10; k++) x[6 + k] = agg[k];
    x[16] = 1.f;

    float h0[5], h1[5], h2[5], o[10];
    #pragma unroll
    for (int k = 0; k < 5; k++) {
        float a = __ldg(bn0 + k);
        #pragma unroll
        for (int i2 = 0; i2 < 17; i2++) a = fmaf(x[i2], __ldg(wn0 + i2 * 5 + k), a);
        h0[k] = frelu(a);
    }
    #pragma unroll
    for (int k = 0; k < 5; k++) {
        float a = __ldg(bn1 + k);
        #pragma unroll
        for (int i2 = 0; i2 < 5; i2++) a = fmaf(h0[i2], __ldg(wn1 + i2 * 5 + k), a);
        h1[k] = frelu(a);
    }
    #pragma unroll
    for (int k = 0; k < 5; k++) {
        float a = __ldg(bn2 + k);
        #pragma unroll
        for (int i2 = 0; i2 < 5; i2++) a = fmaf(h1[i2], __ldg(wn2 + i2 * 5 + k), a);
        h2[k] = frelu(a);
    }
    #pragma unroll
    for (int k = 0; k < 10; k++) {
        float a = __ldg(bn3 + k);
        #pragma unroll
        for (int i2 = 0; i2 < 5; i2++) a = fmaf(h2[i2], __ldg(wn3 + i2 * 10 + k), a);
        o[k] = a;
    }
    float l0 = __ldg(bout + 0), l1 = __ldg(bout + 1);
    #pragma unroll
    for (int i2 = 0; i2 < 10; i2++) {
        l0 = fmaf(o[i2], __ldg(wout + i2 * 2 + 0), l0);
        l1 = fmaf(o[i2], __ldg(wout + i2 * 2 + 1), l1);
    }
    float m = fmaxf(l0, l1);
    float lse = m + logf(expf(l0 - m) + expf(l1 - m));
    float sv = g_label[n];
    out[n] = -((1.f - sv) * (l0 - lse) + sv * (l1 - lse));
}

// ---------------- launch ----------------
extern "C" void kernel_launch(void* const* d_in, const int* in_sizes, int n_in,
                              void* d_out, int out_size)
{
    const float* img = (const float*)d_in[0];
    const float* lab = (const float*)d_in[1];
    const float* msk = (const float*)d_in[2];
    const float* w1  = (const float*)d_in[3];
    const float* b1  = (const float*)d_in[4];
    const float* w2  = (const float*)d_in[5];
    const float* b2  = (const float*)d_in[6];
    const float* d1w = (const float*)d_in[7];
    const float* d1b = (const float*)d_in[8];
    const float* we0 = (const float*)d_in[9];
    const float* be0 = (const float*)d_in[10];
    const float* we1 = (const float*)d_in[11];
    const float* be1 = (const float*)d_in[12];
    const float* we2 = (const float*)d_in[13];
    const float* be2 = (const float*)d_in[14];
    const float* we3 = (const float*)d_in[15];
    const float* be3 = (const float*)d_in[16];
    const float* wn0 = (const float*)d_in[17];
    const float* bn0 = (const float*)d_in[18];
    const float* wn1 = (const float*)d_in[19];
    const float* bn1 = (const float*)d_in[20];
    const float* wn2 = (const float*)d_in[21];
    const float* bn2 = (const float*)d_in[22];
    const float* wn3 = (const float*)d_in[23];
    const float* bn3 = (const float*)d_in[24];
    const float* wout = (const float*)d_in[25];
    const float* bout = (const float*)d_in[26];
    const int* snd = (const int*)d_in[27];
    const int* rcv = (const int*)d_in[28];
    int E = in_sizes[27];

    int smem_bytes = K1_SMEM_FLOATS * (int)sizeof(float);
    cudaFuncSetAttribute(patch_kernel, cudaFuncAttributeMaxDynamicSharedMemorySize, smem_bytes);

    zero_cnt_kernel<<<16, 256>>>();
    patch_kernel<<<4096, 128, smem_bytes>>>(img, lab, msk, w1, b1, w2, b2, d1w, d1b);
    edge_kernel<<<(E + 127) / 128, 128>>>(snd, rcv, E, we0, be0, we1, be1, we2, be2, we3, be3);
    node_kernel<<<32, 128>>>(wn0, bn0, wn1, bn1, wn2, bn2, wn3, bn3, wout, bout, (float*)d_out);

    (void)n_in; (void)out_size;
}

// round 2
// speedup vs baseline: 1.0969x; 1.0969x over previous
#include <cuda_runtime.h>
#include <math.h>
#include <stdint.h>

#define TWO_PI_F 6.2831853071795864769f

// ---------------- scratch (static __device__ allowed) ----------------
__device__ float g_nodes[4096 * 6];
__device__ float g_label[4096];
__device__ float g_efeat[16128 * 10];
__device__ int   g_slot[4096 * 16];
__device__ int   g_cnt[4096];

__device__ __forceinline__ float frelu(float x) { return x > 0.f ? x : 0.f; }
__device__ __forceinline__ float dround(float x) {
    return x - sinf(x * TWO_PI_F) * (1.0f / TWO_PI_F);
}
__device__ __forceinline__ uint32_t smem_u32(const void* p) {
    uint32_t a;
    asm("{ .reg .u64 t; cvta.to.shared.u64 t, %1; cvt.u32.u64 %0, t; }" : "=r"(a) : "l"(p));
    return a;
}
__device__ __forceinline__ void cp_async16(uint32_t dst, const void* src) {
    asm volatile("cp.async.cg.shared.global [%0], [%1], 16;" :: "r"(dst), "l"(src));
}
#define CP_COMMIT() asm volatile("cp.async.commit_group;")
#define CP_WAIT(n)  asm volatile("cp.async.wait_group %0;" :: "n"(n))

// ---------------- kernel 0: zero edge-bucket counters ----------------
__global__ void zero_cnt_kernel() {
    int i = blockIdx.x * 256 + threadIdx.x;
    if (i < 4096) g_cnt[i] = 0;
}

// ---------------- kernel 1: patches + conv1 + conv2 + dense1 ----------------
// grid = 4096 (one patch/node per block), block = 128 threads, 4 blocks/SM
// smem (floats):
//   act1_s [10240]  conv1 out, channel-planar [40][256]; reused as act2 [256][40]
//   w2b    [3200]   conv2 weights double buffer (2 x 1600, one tap each)
//   tok_s  [324]    18x18 zero-padded token tile
//   w1_s   [360], b1_s [40], b2_s [40], red_s [64]
#define K1_SMEM_FLOATS (10240 + 3200 + 324 + 360 + 40 + 40 + 64)

__global__ void __launch_bounds__(128, 4) patch_kernel(
    const float* __restrict__ img, const float* __restrict__ lab,
    const float* __restrict__ msk,
    const float* __restrict__ w1, const float* __restrict__ b1,
    const float* __restrict__ w2, const float* __restrict__ b2,
    const float* __restrict__ d1w, const float* __restrict__ d1b)
{
    extern __shared__ float smem[];
    float* act1_s = smem;
    float* w2b    = smem + 10240;
    float* tok_s  = smem + 13440;
    float* w1_s   = smem + 13764;
    float* b1_s   = smem + 14124;
    float* b2_s   = smem + 14164;
    float* red_s  = smem + 14204;

    const int t = threadIdx.x;
    const int n = blockIdx.x;
    const int g = n >> 10;
    const int ij = n & 1023;
    const int i = ij >> 5, j = ij & 31;
    const int sx = g & 1, sy = g >> 1;            // SHIFTS order (0,0)(1,0)(0,1)(1,1)
    const int r0 = 16 * i + 8 * sx - 4;
    const int c0 = 16 * j + 8 * sy - 4;
    const float cid = (float)((2 * i + sx) * 64 + (2 * j + sy));

    const uint32_t w2b_u = smem_u32(w2b);

    // prefetch conv2 tap 0 weights (overlaps token build + conv1)
    #pragma unroll
    for (int r = 0; r < 4; ++r) {
        int k = t + 128 * r;
        if (k < 400) cp_async16(w2b_u + k * 16, (const float4*)w2 + k);
    }
    CP_COMMIT();

    // stage small weights
    for (int k = t; k < 360; k += 128) w1_s[k] = w1[k];
    if (t < 40) { b1_s[t] = b1[t]; b2_s[t] = b2[t]; }
    for (int k = t; k < 324; k += 128) tok_s[k] = 0.f;
    __syncthreads();

    // tokens (mask-filtered image) + label sums
    float sum_f = 0.f, sum_lp = 0.f;
    #pragma unroll
    for (int pp = 0; pp < 2; ++pp) {
        int p = t + 128 * pp;
        int py = p >> 4, px = p & 15;
        int gr = r0 + py, gc = c0 + px;
        bool inb = (gr >= 0 && gr < 512 && gc >= 0 && gc < 512);
        float m = inb ? msk[gr * 512 + gc] : -1.f;
        float f = (m == cid) ? 1.f : 0.f;
        float iv = (inb ? img[gr * 512 + gc] : 0.f) * f;
        float lv = (inb ? lab[gr * 512 + gc] : 0.f) * f;
        tok_s[(py + 1) * 18 + px + 1] = iv;
        sum_f += f; sum_lp += lv;
    }
    #pragma unroll
    for (int o = 16; o; o >>= 1) {
        sum_f  += __shfl_down_sync(0xffffffffu, sum_f, o);
        sum_lp += __shfl_down_sync(0xffffffffu, sum_lp, o);
    }
    if ((t & 31) == 0) { red_s[(t >> 5) * 2] = sum_f; red_s[(t >> 5) * 2 + 1] = sum_lp; }
    __syncthreads();
    if (t == 0) {
        float sf = red_s[0] + red_s[2] + red_s[4] + red_s[6];
        float sl = red_s[1] + red_s[3] + red_s[5] + red_s[7];
        g_label[n] = dround(dround(sl / (sf + 1e-8f)));
    }

    // ---- conv1: 1 -> 40, 3x3 SAME, relu; store channel-planar [c][p] ----
    #pragma unroll
    for (int pp = 0; pp < 2; ++pp) {
        int p = t + 128 * pp;
        int py = p >> 4, px = p & 15;
        float t9[9];
        #pragma unroll
        for (int k = 0; k < 9; k++) t9[k] = tok_s[(py + k / 3) * 18 + px + (k % 3)];
        #pragma unroll 8
        for (int c = 0; c < 40; c++) {
            float s = b1_s[c];
            #pragma unroll
            for (int k = 0; k < 9; k++) s = fmaf(t9[k], w1_s[k * 40 + c], s);
            act1_s[c * 256 + p] = frelu(s);
        }
    }

    // ---- conv2: tap-streamed weights, register-tiled, f32x2 packed FMA ----
    // warp w owns cos [10w, 10w+10); lane l owns pixels {32jj + l}
    const int w  = t >> 5, l = t & 31;
    const int px = l & 15, py0 = l >> 4;

    unsigned long long acc[8][5];
    #pragma unroll
    for (int jj = 0; jj < 8; jj++)
        #pragma unroll
        for (int q = 0; q < 5; q++) acc[jj][q] = 0ull;

    for (int tap = 0; tap < 9; ++tap) {
        __syncthreads();      // prior readers of the buffer we are about to fill are done
        if (tap < 8) {
            uint32_t dst = w2b_u + ((tap + 1) & 1) * 6400;
            const float4* src = (const float4*)(w2 + (tap + 1) * 1600);
            #pragma unroll
            for (int r = 0; r < 4; ++r) {
                int k = t + 128 * r;
                if (k < 400) cp_async16(dst + k * 16, src + k);
            }
            CP_COMMIT();
            CP_WAIT(1);       // current tap's buffer complete
        } else {
            CP_WAIT(0);
        }
        __syncthreads();      // current tap's weights visible to all

        const int dy = tap / 3 - 1, dx = tap % 3 - 1;
        const int xx = px + dx;
        const bool vx = ((unsigned)xx < 16u);
        int base[8]; bool vld[8];
        #pragma unroll
        for (int jj = 0; jj < 8; jj++) {
            int yy = 2 * jj + py0 + dy;
            vld[jj] = vx && ((unsigned)yy < 16u);
            base[jj] = yy * 16 + xx;
        }
        const float* wp = w2b + (tap & 1) * 1600 + 10 * w;
        const float* ap = act1_s;
        #pragma unroll 2
        for (int ci = 0; ci < 40; ++ci) {
            unsigned long long wv[5];
            #pragma unroll
            for (int q = 0; q < 5; q++)
                wv[q] = *(const unsigned long long*)(wp + 2 * q);
            #pragma unroll
            for (int jj = 0; jj < 8; jj++) {
                float a = vld[jj] ? ap[base[jj]] : 0.f;
                unsigned long long a2;
                asm("mov.b64 %0, {%1, %2};" : "=l"(a2) : "f"(a), "f"(a));
                #pragma unroll
                for (int q = 0; q < 5; q++)
                    asm("fma.rn.f32x2 %0, %1, %2, %0;"
                        : "+l"(acc[jj][q]) : "l"(a2), "l"(wv[q]));
            }
            wp += 40; ap += 256;
        }
    }
    __syncthreads();   // all reads of act1 planes done

    // act2 = relu(acc + b2) stored flat [p*40 + co] (reuse act1_s)
    #pragma unroll
    for (int jj = 0; jj < 8; jj++) {
        int p = 32 * jj + l;
        #pragma unroll
        for (int q = 0; q < 5; q++) {
            float lo, hi;
            asm("mov.b64 {%0, %1}, %2;" : "=f"(lo), "=f"(hi) : "l"(acc[jj][q]));
            int co = 10 * w + 2 * q;
            float2 v = make_float2(frelu(lo + b2_s[co]), frelu(hi + b2_s[co + 1]));
            *(float2*)(act1_s + p * 40 + co) = v;
        }
    }
    __syncthreads();

    // ---- dense1: 10240 -> 6 cooperative GEMV (float2 weight loads) ----
    float part[6] = {0.f, 0.f, 0.f, 0.f, 0.f, 0.f};
    for (int m = 0; m < 80; ++m) {
        int idx = t + 128 * m;
        float v = act1_s[idx];
        const float2* wr = (const float2*)(d1w + idx * 6);
        float2 w01 = __ldg(wr), w23 = __ldg(wr + 1), w45 = __ldg(wr + 2);
        part[0] = fmaf(v, w01.x, part[0]);
        part[1] = fmaf(v, w01.y, part[1]);
        part[2] = fmaf(v, w23.x, part[2]);
        part[3] = fmaf(v, w23.y, part[3]);
        part[4] = fmaf(v, w45.x, part[4]);
        part[5] = fmaf(v, w45.y, part[5]);
    }
    #pragma unroll
    for (int k = 0; k < 6; k++)
        #pragma unroll
        for (int o = 16; o; o >>= 1) part[k] += __shfl_down_sync(0xffffffffu, part[k], o);
    if (l == 0) {
        #pragma unroll
        for (int k = 0; k < 6; k++) red_s[w * 6 + k] = part[k];
    }
    __syncthreads();
    if (t < 6) {
        float s = red_s[t] + red_s[6 + t] + red_s[12 + t] + red_s[18 + t];
        g_nodes[n * 6 + t] = frelu(s + d1b[t]);
    }
}

// ---------------- kernel 2: edge MLP + deterministic bucketing ----------------
__global__ void __launch_bounds__(128) edge_kernel(
    const int* __restrict__ snd, const int* __restrict__ rcv, int E,
    const float* __restrict__ we0, const float* __restrict__ be0,
    const float* __restrict__ we1, const float* __restrict__ be1,
    const float* __restrict__ we2, const float* __restrict__ be2,
    const float* __restrict__ we3, const float* __restrict__ be3)
{
    int e = blockIdx.x * 128 + threadIdx.x;
    if (e >= E) return;
    int s = snd[e], r = rcv[e];
    float x[13];
    #pragma unroll
    for (int k = 0; k < 6; k++) { x[k] = g_nodes[s * 6 + k]; x[6 + k] = g_nodes[r * 6 + k]; }
    x[12] = 1.f;

    float h0[5], h1[5], h2[5];
    #pragma unroll
    for (int k = 0; k < 5; k++) {
        float a = __ldg(be0 + k);
        #pragma unroll
        for (int i2 = 0; i2 < 13; i2++) a = fmaf(x[i2], __ldg(we0 + i2 * 5 + k), a);
        h0[k] = frelu(a);
    }
    #pragma unroll
    for (int k = 0; k < 5; k++) {
        float a = __ldg(be1 + k);
        #pragma unroll
        for (int i2 = 0; i2 < 5; i2++) a = fmaf(h0[i2], __ldg(we1 + i2 * 5 + k), a);
        h1[k] = frelu(a);
    }
    #pragma unroll
    for (int k = 0; k < 5; k++) {
        float a = __ldg(be2 + k);
        #pragma unroll
        for (int i2 = 0; i2 < 5; i2++) a = fmaf(h1[i2], __ldg(we2 + i2 * 5 + k), a);
        h2[k] = frelu(a);
    }
    #pragma unroll
    for (int k = 0; k < 10; k++) {
        float a = __ldg(be3 + k);
        #pragma unroll
        for (int i2 = 0; i2 < 5; i2++) a = fmaf(h2[i2], __ldg(we3 + i2 * 10 + k), a);
        g_efeat[e * 10 + k] = a;
    }
    int pos = atomicAdd(&g_cnt[r], 1);
    if (pos < 16) g_slot[r * 16 + pos] = e;
}

// ---------------- kernel 3: deterministic agg + node MLP + CE loss ----------------
__global__ void __launch_bounds__(32) node_kernel(
    const float* __restrict__ wn0, const float* __restrict__ bn0,
    const float* __restrict__ wn1, const float* __restrict__ bn1,
    const float* __restrict__ wn2, const float* __restrict__ bn2,
    const float* __restrict__ wn3, const float* __restrict__ bn3,
    const float* __restrict__ wout, const float* __restrict__ bout,
    float* __restrict__ out)
{
    int n = blockIdx.x * 32 + threadIdx.x;
    if (n >= 4096) return;

    int d = g_cnt[n]; if (d > 16) d = 16;
    int ids[16];
    for (int a = 0; a < d; a++) ids[a] = g_slot[n * 16 + a];
    // insertion sort by edge id -> deterministic summation order
    for (int a = 1; a < d; a++) {
        int key = ids[a]; int b = a - 1;
        while (b >= 0 && ids[b] > key) { ids[b + 1] = ids[b]; b--; }
        ids[b + 1] = key;
    }
    float agg[10];
    #pragma unroll
    for (int k = 0; k < 10; k++) agg[k] = 0.f;
    for (int a = 0; a < d; a++) {
        int e = ids[a];
        #pragma unroll
        for (int k = 0; k < 10; k++) agg[k] += g_efeat[e * 10 + k];
    }

    float x[17];
    #pragma unroll
    for (int k = 0; k < 6; k++) x[k] = g_nodes[n * 6 + k];
    #pragma unroll
    for (int k = 0; k < 10; k++) x[6 + k] = agg[k];
    x[16] = 1.f;

    float h0[5], h1[5], h2[5], o[10];
    #pragma unroll
    for (int k = 0; k < 5; k++) {
        float a = __ldg(bn0 + k);
        #pragma unroll
        for (int i2 = 0; i2 < 17; i2++) a = fmaf(x[i2], __ldg(wn0 + i2 * 5 + k), a);
        h0[k] = frelu(a);
    }
    #pragma unroll
    for (int k = 0; k < 5; k++) {
        float a = __ldg(bn1 + k);
        #pragma unroll
        for (int i2 = 0; i2 < 5; i2++) a = fmaf(h0[i2], __ldg(wn1 + i2 * 5 + k), a);
        h1[k] = frelu(a);
    }
    #pragma unroll
    for (int k = 0; k < 5; k++) {
        float a = __ldg(bn2 + k);
        #pragma unroll
        for (int i2 = 0; i2 < 5; i2++) a = fmaf(h1[i2], __ldg(wn2 + i2 * 5 + k), a);
        h2[k] = frelu(a);
    }
    #pragma unroll
    for (int k = 0; k < 10; k++) {
        float a = __ldg(bn3 + k);
        #pragma unroll
        for (int i2 = 0; i2 < 5; i2++) a = fmaf(h2[i2], __ldg(wn3 + i2 * 10 + k), a);
        o[k] = a;
    }
    float l0 = __ldg(bout + 0), l1 = __ldg(bout + 1);
    #pragma unroll
    for (int i2 = 0; i2 < 10; i2++) {
        l0 = fmaf(o[i2], __ldg(wout + i2 * 2 + 0), l0);
        l1 = fmaf(o[i2], __ldg(wout + i2 * 2 + 1), l1);
    }
    float m = fmaxf(l0, l1);
    float lse = m + logf(expf(l0 - m) + expf(l1 - m));
    float sv = g_label[n];
    out[n] = -((1.f - sv) * (l0 - lse) + sv * (l1 - lse));
}

// ---------------- launch ----------------
extern "C" void kernel_launch(void* const* d_in, const int* in_sizes, int n_in,
                              void* d_out, int out_size)
{
    const float* img = (const float*)d_in[0];
    const float* lab = (const float*)d_in[1];
    const float* msk = (const float*)d_in[2];
    const float* w1  = (const float*)d_in[3];
    const float* b1  = (const float*)d_in[4];
    const float* w2  = (const float*)d_in[5];
    const float* b2  = (const float*)d_in[6];
    const float* d1w = (const float*)d_in[7];
    const float* d1b = (const float*)d_in[8];
    const float* we0 = (const float*)d_in[9];
    const float* be0 = (const float*)d_in[10];
    const float* we1 = (const float*)d_in[11];
    const float* be1 = (const float*)d_in[12];
    const float* we2 = (const float*)d_in[13];
    const float* be2 = (const float*)d_in[14];
    const float* we3 = (const float*)d_in[15];
    const float* be3 = (const float*)d_in[16];
    const float* wn0 = (const float*)d_in[17];
    const float* bn0 = (const float*)d_in[18];
    const float* wn1 = (const float*)d_in[19];
    const float* bn1 = (const float*)d_in[20];
    const float* wn2 = (const float*)d_in[21];
    const float* bn2 = (const float*)d_in[22];
    const float* wn3 = (const float*)d_in[23];
    const float* bn3 = (const float*)d_in[24];
    const float* wout = (const float*)d_in[25];
    const float* bout = (const float*)d_in[26];
    const int* snd = (const int*)d_in[27];
    const int* rcv = (const int*)d_in[28];
    int E = in_sizes[27];

    int smem_bytes = K1_SMEM_FLOATS * (int)sizeof(float);
    static int configured = -1;
    if (configured != smem_bytes) {
        cudaFuncSetAttribute(patch_kernel, cudaFuncAttributeMaxDynamicSharedMemorySize, smem_bytes);
        configured = smem_bytes;
    }

    zero_cnt_kernel<<<16, 256>>>();
    patch_kernel<<<4096, 128, smem_bytes>>>(img, lab, msk, w1, b1, w2, b2, d1w, d1b);
    edge_kernel<<<(E + 127) / 128, 128>>>(snd, rcv, E, we0, be0, we1, be1, we2, be2, we3, be3);
    node_kernel<<<128, 32>>>(wn0, bn0, wn1, bn1, wn2, bn2, wn3, bn3, wout, bout, (float*)d_out);

    (void)n_in; (void)out_size;
}

// round 3
// speedup vs baseline: 1.6000x; 1.4587x over previous
#include <cuda_runtime.h>
#include <math.h>
#include <stdint.h>

#define TWO_PI_F 6.2831853071795864769f

// ---------------- scratch ----------------
__device__ float g_nodes[4096 * 6];
__device__ float g_label[4096];
__device__ float g_efeat[16128 * 10];
__device__ int   g_slot[4096 * 16];
__device__ int   g_cnt[4096];
// per-launch precompute
__device__ float g_c2[40];                 // b2 + sum_taps T  (interior base)
__device__ float g_extk[6];                // exterior pixels' dense1 contribution
__device__ float2 g_wint[3 * 5760];        // interior dense1 weights [k-pair][f]

__device__ __forceinline__ float frelu(float x) { return x > 0.f ? x : 0.f; }
__device__ __forceinline__ float dround(float x) {
    return x - sinf(x * TWO_PI_F) * (1.0f / TWO_PI_F);
}
__device__ __forceinline__ uint32_t smem_u32(const void* p) {
    uint32_t a;
    asm("{ .reg .u64 t; cvta.to.shared.u64 t, %1; cvt.u32.u64 %0, t; }" : "=r"(a) : "l"(p));
    return a;
}
__device__ __forceinline__ void cp_async16(uint32_t dst, const void* src) {
    asm volatile("cp.async.cg.shared.global [%0], [%1], 16;" :: "r"(dst), "l"(src));
}
#define CP_COMMIT() asm volatile("cp.async.commit_group;")
#define CP_WAIT(n)  asm volatile("cp.async.wait_group %0;" :: "n"(n))

// ---------------- kernel -1: precompute (input-dependent, rerun every launch) ----------------
// block 0: T[9][40], g_c2, E[9][40], g_extk ; blocks 1..45: g_wint gather
__global__ void __launch_bounds__(128) pre_kernel(
    const float* __restrict__ b1, const float* __restrict__ w2,
    const float* __restrict__ b2, const float* __restrict__ d1w)
{
    const int t = threadIdx.x;
    if (blockIdx.x == 0) {
        __shared__ float T[360];     // [tap][co]
        __shared__ float E[360];     // [cls][co], cls = yc*3+xc
        __shared__ float R[6][128];
        for (int item = t; item < 360; item += 128) {
            int tap = item / 40, co = item - 40 * tap;
            float s = 0.f;
            for (int ci = 0; ci < 40; ci++)
                s = fmaf(frelu(b1[ci]), w2[tap * 1600 + ci * 40 + co], s);
            T[item] = s;
        }
        __syncthreads();
        if (t < 40) {
            float s = b2[t];
            #pragma unroll
            for (int tap = 0; tap < 9; tap++) s += T[tap * 40 + t];
            g_c2[t] = s;
        }
        for (int item = t; item < 360; item += 128) {
            int cls = item / 40, co = item - 40 * cls;
            int yc = cls / 3, xc = cls - 3 * yc;
            float s = b2[co];
            #pragma unroll
            for (int tap = 0; tap < 9; tap++) {
                int dy = tap / 3, dx = tap % 3;   // 0,1,2 (offset-1)
                bool vy = !((yc == 0 && dy == 0) || (yc == 2 && dy == 2));
                bool vx = !((xc == 0 && dx == 0) || (xc == 2 && dx == 2));
                if (vy && vx) s += T[tap * 40 + co];
            }
            E[item] = frelu(s);
        }
        __syncthreads();
        float loc[6] = {0.f, 0.f, 0.f, 0.f, 0.f, 0.f};
        for (int p = t; p < 256; p += 128) {
            int y = p >> 4, x = p & 15;
            if (y >= 2 && y <= 13 && x >= 2 && x <= 13) continue;  // interior
            int yc = (y == 0) ? 0 : (y == 15 ? 2 : 1);
            int xc = (x == 0) ? 0 : (x == 15 ? 2 : 1);
            const float* Ec = E + (yc * 3 + xc) * 40;
            for (int co = 0; co < 40; co++) {
                float v = Ec[co];
                const float* wr = d1w + (p * 40 + co) * 6;
                #pragma unroll
                for (int k = 0; k < 6; k++) loc[k] = fmaf(v, wr[k], loc[k]);
            }
        }
        #pragma unroll
        for (int k = 0; k < 6; k++) R[k][t] = loc[k];
        __syncthreads();
        if (t < 6) {
            float s = 0.f;
            for (int i = 0; i < 128; i++) s += R[t][i];
            g_extk[t] = s;
        }
    } else {
        int f = (blockIdx.x - 1) * 128 + t;   // 45 blocks * 128 = 5760
        int q = f / 40, co = f - 40 * q;
        int p = (2 + q / 12) * 16 + (2 + q % 12);
        const float* wr = d1w + (p * 40 + co) * 6;
        #pragma unroll
        for (int k2 = 0; k2 < 3; k2++)
            g_wint[k2 * 5760 + f] = make_float2(wr[2 * k2], wr[2 * k2 + 1]);
    }
}

// ---------------- kernel 0: zero edge-bucket counters ----------------
__global__ void zero_cnt_kernel() {
    int i = blockIdx.x * 256 + threadIdx.x;
    if (i < 4096) g_cnt[i] = 0;
}

// ---------------- kernel 1: patches + delta-conv1 + delta-conv2 + dense1 ----------------
// grid 4096, block 128, 5 blocks/SM. smem (floats):
//   A     [5760]  union: D planes [40][120] (conv2 input)  /  act2 interior [144][40]
//   w2b   [3200]  conv2 weight double buffer
//   tok_s [324], w1_s [360], b1_s [40], c2s [40], red_s [64]
#define K1_SMEM_FLOATS (5760 + 3200 + 324 + 360 + 40 + 40 + 64)

__global__ void __launch_bounds__(128, 5) patch_kernel(
    const float* __restrict__ img, const float* __restrict__ lab,
    const float* __restrict__ msk,
    const float* __restrict__ w1, const float* __restrict__ b1,
    const float* __restrict__ w2, const float* __restrict__ d1b)
{
    extern __shared__ float smem[];
    float* A     = smem;
    float* w2b   = smem + 5760;
    float* tok_s = smem + 8960;
    float* w1_s  = smem + 9284;
    float* b1_s  = smem + 9644;
    float* c2s   = smem + 9684;
    float* red_s = smem + 9724;

    const int t = threadIdx.x;
    const int n = blockIdx.x;
    const int g = n >> 10;
    const int ij = n & 1023;
    const int i = ij >> 5, j = ij & 31;
    const int sx = g & 1, sy = g >> 1;
    const int r0 = 16 * i + 8 * sx - 4;
    const int c0 = 16 * j + 8 * sy - 4;
    const float cid = (float)((2 * i + sx) * 64 + (2 * j + sy));

    const uint32_t w2b_u = smem_u32(w2b);

    // prefetch conv2 tap 0 weights
    #pragma unroll
    for (int r = 0; r < 4; ++r) {
        int k = t + 128 * r;
        if (k < 400) cp_async16(w2b_u + k * 16, (const float4*)w2 + k);
    }
    CP_COMMIT();

    for (int k = t; k < 360; k += 128) w1_s[k] = w1[k];
    if (t < 40) { b1_s[t] = b1[t]; c2s[t] = g_c2[t]; }
    for (int k = t; k < 324; k += 128) tok_s[k] = 0.f;
    __syncthreads();

    // tokens + label sums
    float sum_f = 0.f, sum_lp = 0.f;
    #pragma unroll
    for (int pp = 0; pp < 2; ++pp) {
        int p = t + 128 * pp;
        int py = p >> 4, px = p & 15;
        int gr = r0 + py, gc = c0 + px;
        bool inb = (gr >= 0 && gr < 512 && gc >= 0 && gc < 512);
        float m = inb ? msk[gr * 512 + gc] : -1.f;
        float f = (m == cid) ? 1.f : 0.f;
        float iv = (inb ? img[gr * 512 + gc] : 0.f) * f;
        float lv = (inb ? lab[gr * 512 + gc] : 0.f) * f;
        tok_s[(py + 1) * 18 + px + 1] = iv;
        sum_f += f; sum_lp += lv;
    }
    #pragma unroll
    for (int o = 16; o; o >>= 1) {
        sum_f  += __shfl_down_sync(0xffffffffu, sum_f, o);
        sum_lp += __shfl_down_sync(0xffffffffu, sum_lp, o);
    }
    if ((t & 31) == 0) { red_s[(t >> 5) * 2] = sum_f; red_s[(t >> 5) * 2 + 1] = sum_lp; }
    __syncthreads();
    if (t == 0) {
        float sf = red_s[0] + red_s[2] + red_s[4] + red_s[6];
        float sl = red_s[1] + red_s[3] + red_s[5] + red_s[7];
        g_label[n] = dround(dround(sl / (sf + 1e-8f)));
    }

    // ---- conv1 delta: D[c][(r-3)*12+(c-3)] on 10x10 (patch rows/cols 3..12) ----
    if (t < 100) {
        int rr = 3 + t / 10, cc = 3 + t - 10 * (t / 10);
        float t9[9];
        #pragma unroll
        for (int k = 0; k < 9; k++) t9[k] = tok_s[(rr + k / 3) * 18 + (cc + k % 3)];
        int dpos = (rr - 3) * 12 + (cc - 3);
        #pragma unroll 8
        for (int c = 0; c < 40; c++) {
            float s = 0.f;
            #pragma unroll
            for (int k = 0; k < 9; k++) s = fmaf(t9[k], w1_s[k * 40 + c], s);
            float b = b1_s[c];
            A[c * 120 + dpos] = frelu(b + s) - frelu(b);
        }
    }

    // ---- conv2 delta: 144 output px (rows/cols 2..13), f32x2 FMA ----
    const int w = t >> 5, l = t & 31;

    unsigned long long acc[5][5];
    #pragma unroll
    for (int jj = 0; jj < 5; jj++)
        #pragma unroll
        for (int q2 = 0; q2 < 5; q2++) acc[jj][q2] = 0ull;

    for (int tap = 0; tap < 9; ++tap) {
        __syncthreads();
        if (tap < 8) {
            uint32_t dst = w2b_u + ((tap + 1) & 1) * 6400;
            const float4* src = (const float4*)(w2 + (tap + 1) * 1600);
            #pragma unroll
            for (int r = 0; r < 4; ++r) {
                int k = t + 128 * r;
                if (k < 400) cp_async16(dst + k * 16, src + k);
            }
            CP_COMMIT();
            CP_WAIT(1);
        } else {
            CP_WAIT(0);
        }
        __syncthreads();

        const int dy = tap / 3 - 1, dx = tap % 3 - 1;
        int di[5]; bool vld[5];
        #pragma unroll
        for (int jj = 0; jj < 5; jj++) {
            int q = 32 * jj + l;
            int oy = 2 + q / 12, ox = 2 + q - 12 * (q / 12);
            int iy = oy + dy - 3, ix = ox + dx - 3;
            vld[jj] = (q < 144) && ((unsigned)iy < 10u) && ((unsigned)ix < 10u);
            di[jj] = iy * 12 + ix;
        }
        const float* wp = w2b + (tap & 1) * 1600 + 10 * w;
        const float* Dp = A;
        #pragma unroll 2
        for (int ci = 0; ci < 40; ++ci) {
            unsigned long long wv[5];
            #pragma unroll
            for (int q2 = 0; q2 < 5; q2++)
                wv[q2] = *(const unsigned long long*)(wp + 2 * q2);
            #pragma unroll
            for (int jj = 0; jj < 5; jj++) {
                float a = vld[jj] ? Dp[di[jj]] : 0.f;
                unsigned long long a2;
                asm("mov.b64 %0, {%1, %2};" : "=l"(a2) : "f"(a), "f"(a));
                #pragma unroll
                for (int q2 = 0; q2 < 5; q2++)
                    asm("fma.rn.f32x2 %0, %1, %2, %0;"
                        : "+l"(acc[jj][q2]) : "l"(a2), "l"(wv[q2]));
            }
            wp += 40; Dp += 120;
        }
    }
    __syncthreads();   // all D reads done; A may be overwritten

    // epilogue: act2 interior = relu(c2 + delta) -> A[q*40+co]
    #pragma unroll
    for (int jj = 0; jj < 5; jj++) {
        int q = 32 * jj + l;
        if (q < 144) {
            #pragma unroll
            for (int q2 = 0; q2 < 5; q2++) {
                float lo, hi;
                asm("mov.b64 {%0, %1}, %2;" : "=f"(lo), "=f"(hi) : "l"(acc[jj][q2]));
                int co = 10 * w + 2 * q2;
                float2 v = make_float2(frelu(lo + c2s[co]), frelu(hi + c2s[co + 1]));
                *(float2*)(A + q * 40 + co) = v;
            }
        }
    }
    __syncthreads();

    // ---- dense1 interior: 5760 elements, pre-gathered packed weights ----
    const unsigned long long* wt = (const unsigned long long*)g_wint;
    unsigned long long p3[3] = {0ull, 0ull, 0ull};
    for (int m = 0; m < 45; ++m) {
        int f = t + 128 * m;
        float v = A[f];
        unsigned long long a2;
        asm("mov.b64 %0, {%1, %2};" : "=l"(a2) : "f"(v), "f"(v));
        #pragma unroll
        for (int k2 = 0; k2 < 3; k2++) {
            unsigned long long wv = __ldg(wt + k2 * 5760 + f);
            asm("fma.rn.f32x2 %0, %1, %2, %0;" : "+l"(p3[k2]) : "l"(a2), "l"(wv));
        }
    }
    float part[6];
    #pragma unroll
    for (int k2 = 0; k2 < 3; k2++)
        asm("mov.b64 {%0, %1}, %2;" : "=f"(part[2 * k2]), "=f"(part[2 * k2 + 1]) : "l"(p3[k2]));
    #pragma unroll
    for (int k = 0; k < 6; k++)
        #pragma unroll
        for (int o = 16; o; o >>= 1) part[k] += __shfl_down_sync(0xffffffffu, part[k], o);
    if (l == 0) {
        #pragma unroll
        for (int k = 0; k < 6; k++) red_s[w * 6 + k] = part[k];
    }
    __syncthreads();
    if (t < 6) {
        float s = red_s[t] + red_s[6 + t] + red_s[12 + t] + red_s[18 + t];
        g_nodes[n * 6 + t] = frelu(s + g_extk[t] + d1b[t]);
    }
}

// ---------------- kernel 2: edge MLP + deterministic bucketing ----------------
__global__ void __launch_bounds__(128) edge_kernel(
    const int* __restrict__ snd, const int* __restrict__ rcv, int E,
    const float* __restrict__ we0, const float* __restrict__ be0,
    const float* __restrict__ we1, const float* __restrict__ be1,
    const float* __restrict__ we2, const float* __restrict__ be2,
    const float* __restrict__ we3, const float* __restrict__ be3)
{
    int e = blockIdx.x * 128 + threadIdx.x;
    if (e >= E) return;
    int s = snd[e], r = rcv[e];
    float x[13];
    #pragma unroll
    for (int k = 0; k < 6; k++) { x[k] = g_nodes[s * 6 + k]; x[6 + k] = g_nodes[r * 6 + k]; }
    x[12] = 1.f;

    float h0[5], h1[5], h2[5];
    #pragma unroll
    for (int k = 0; k < 5; k++) {
        float a = __ldg(be0 + k);
        #pragma unroll
        for (int i2 = 0; i2 < 13; i2++) a = fmaf(x[i2], __ldg(we0 + i2 * 5 + k), a);
        h0[k] = frelu(a);
    }
    #pragma unroll
    for (int k = 0; k < 5; k++) {
        float a = __ldg(be1 + k);
        #pragma unroll
        for (int i2 = 0; i2 < 5; i2++) a = fmaf(h0[i2], __ldg(we1 + i2 * 5 + k), a);
        h1[k] = frelu(a);
    }
    #pragma unroll
    for (int k = 0; k < 5; k++) {
        float a = __ldg(be2 + k);
        #pragma unroll
        for (int i2 = 0; i2 < 5; i2++) a = fmaf(h1[i2], __ldg(we2 + i2 * 5 + k), a);
        h2[k] = frelu(a);
    }
    #pragma unroll
    for (int k = 0; k < 10; k++) {
        float a = __ldg(be3 + k);
        #pragma unroll
        for (int i2 = 0; i2 < 5; i2++) a = fmaf(h2[i2], __ldg(we3 + i2 * 10 + k), a);
        g_efeat[e * 10 + k] = a;
    }
    int pos = atomicAdd(&g_cnt[r], 1);
    if (pos < 16) g_slot[r * 16 + pos] = e;
}

// ---------------- kernel 3: deterministic agg + node MLP + CE loss ----------------
__global__ void __launch_bounds__(32) node_kernel(
    const float* __restrict__ wn0, const float* __restrict__ bn0,
    const float* __restrict__ wn1, const float* __restrict__ bn1,
    const float* __restrict__ wn2, const float* __restrict__ bn2,
    const float* __restrict__ wn3, const float* __restrict__ bn3,
    const float* __restrict__ wout, const float* __restrict__ bout,
    float* __restrict__ out)
{
    int n = blockIdx.x * 32 + threadIdx.x;
    if (n >= 4096) return;

    int d = g_cnt[n]; if (d > 16) d = 16;
    int ids[16];
    for (int a = 0; a < d; a++) ids[a] = g_slot[n * 16 + a];
    for (int a = 1; a < d; a++) {
        int key = ids[a]; int b = a - 1;
        while (b >= 0 && ids[b] > key) { ids[b + 1] = ids[b]; b--; }
        ids[b + 1] = key;
    }
    float agg[10];
    #pragma unroll
    for (int k = 0; k < 10; k++) agg[k] = 0.f;
    for (int a = 0; a < d; a++) {
        int e = ids[a];
        #pragma unroll
        for (int k = 0; k < 10; k++) agg[k] += g_efeat[e * 10 + k];
    }

    float x[17];
    #pragma unroll
    for (int k = 0; k < 6; k++) x[k] = g_nodes[n * 6 + k];
    #pragma unroll
    for (int k = 0; k < 10; k++) x[6 + k] = agg[k];
    x[16] = 1.f;

    float h0[5], h1[5], h2[5], o[10];
    #pragma unroll
    for (int k = 0; k < 5; k++) {
        float a = __ldg(bn0 + k);
        #pragma unroll
        for (int i2 = 0; i2 < 17; i2++) a = fmaf(x[i2], __ldg(wn0 + i2 * 5 + k), a);
        h0[k] = frelu(a);
    }
    #pragma unroll
    for (int k = 0; k < 5; k++) {
        float a = __ldg(bn1 + k);
        #pragma unroll
        for (int i2 = 0; i2 < 5; i2++) a = fmaf(h0[i2], __ldg(wn1 + i2 * 5 + k), a);
        h1[k] = frelu(a);
    }
    #pragma unroll
    for (int k = 0; k < 5; k++) {
        float a = __ldg(bn2 + k);
        #pragma unroll
        for (int i2 = 0; i2 < 5; i2++) a = fmaf(h1[i2], __ldg(wn2 + i2 * 5 + k), a);
        h2[k] = frelu(a);
    }
    #pragma unroll
    for (int k = 0; k < 10; k++) {
        float a = __ldg(bn3 + k);
        #pragma unroll
        for (int i2 = 0; i2 < 5; i2++) a = fmaf(h2[i2], __ldg(wn3 + i2 * 10 + k), a);
        o[k] = a;
    }
    float l0 = __ldg(bout + 0), l1 = __ldg(bout + 1);
    #pragma unroll
    for (int i2 = 0; i2 < 10; i2++) {
        l0 = fmaf(o[i2], __ldg(wout + i2 * 2 + 0), l0);
        l1 = fmaf(o[i2], __ldg(wout + i2 * 2 + 1), l1);
    }
    float m = fmaxf(l0, l1);
    float lse = m + logf(expf(l0 - m) + expf(l1 - m));
    float sv = g_label[n];
    out[n] = -((1.f - sv) * (l0 - lse) + sv * (l1 - lse));
}

// ---------------- launch ----------------
extern "C" void kernel_launch(void* const* d_in, const int* in_sizes, int n_in,
                              void* d_out, int out_size)
{
    const float* img = (const float*)d_in[0];
    const float* lab = (const float*)d_in[1];
    const float* msk = (const float*)d_in[2];
    const float* w1  = (const float*)d_in[3];
    const float* b1  = (const float*)d_in[4];
    const float* w2  = (const float*)d_in[5];
    const float* b2  = (const float*)d_in[6];
    const float* d1w = (const float*)d_in[7];
    const float* d1b = (const float*)d_in[8];
    const float* we0 = (const float*)d_in[9];
    const float* be0 = (const float*)d_in[10];
    const float* we1 = (const float*)d_in[11];
    const float* be1 = (const float*)d_in[12];
    const float* we2 = (const float*)d_in[13];
    const float* be2 = (const float*)d_in[14];
    const float* we3 = (const float*)d_in[15];
    const float* be3 = (const float*)d_in[16];
    const float* wn0 = (const float*)d_in[17];
    const float* bn0 = (const float*)d_in[18];
    const float* wn1 = (const float*)d_in[19];
    const float* bn1 = (const float*)d_in[20];
    const float* wn2 = (const float*)d_in[21];
    const float* bn2 = (const float*)d_in[22];
    const float* wn3 = (const float*)d_in[23];
    const float* bn3 = (const float*)d_in[24];
    const float* wout = (const float*)d_in[25];
    const float* bout = (const float*)d_in[26];
    const int* snd = (const int*)d_in[27];
    const int* rcv = (const int*)d_in[28];
    int E = in_sizes[27];

    int smem_bytes = K1_SMEM_FLOATS * (int)sizeof(float);
    static int configured = -1;
    if (configured != smem_bytes) {
        cudaFuncSetAttribute(patch_kernel, cudaFuncAttributeMaxDynamicSharedMemorySize, smem_bytes);
        configured = smem_bytes;
    }

    pre_kernel<<<46, 128>>>(b1, w2, b2, d1w);
    zero_cnt_kernel<<<16, 256>>>();
    patch_kernel<<<4096, 128, smem_bytes>>>(img, lab, msk, w1, b1, w2, d1b);
    edge_kernel<<<(E + 127) / 128, 128>>>(snd, rcv, E, we0, be0, we1, be1, we2, be2, we3, be3);
    node_kernel<<<128, 32>>>(wn0, bn0, wn1, bn1, wn2, bn2, wn3, bn3, wout, bout, (float*)d_out);

    (void)n_in; (void)out_size;
}

// round 4
// speedup vs baseline: 1.7412x; 1.0882x over previous
#include <cuda_runtime.h>
#include <math.h>
#include <stdint.h>

#define TWO_PI_F 6.2831853071795864769f

// ---------------- scratch ----------------
__device__ float g_nodes[4096 * 6];
__device__ float g_label[4096];
__device__ float g_efeat[16128 * 10];
__device__ int   g_slot[4096 * 16];
__device__ int   g_cnt[4096];
// per-launch precompute
__device__ float g_c2[40];                 // b2 + sum_taps T  (interior base)
__device__ float g_extk[6];                // exterior pixels' dense1 contribution
__device__ float2 g_wint[3 * 5760];        // interior dense1 weights [k-pair][f]

__device__ __forceinline__ float frelu(float x) { return x > 0.f ? x : 0.f; }
__device__ __forceinline__ float dround(float x) {
    return x - sinf(x * TWO_PI_F) * (1.0f / TWO_PI_F);
}
__device__ __forceinline__ uint32_t smem_u32(const void* p) {
    uint32_t a;
    asm("{ .reg .u64 t; cvta.to.shared.u64 t, %1; cvt.u32.u64 %0, t; }" : "=r"(a) : "l"(p));
    return a;
}
__device__ __forceinline__ void cp_async16(uint32_t dst, const void* src) {
    asm volatile("cp.async.cg.shared.global [%0], [%1], 16;" :: "r"(dst), "l"(src));
}
#define CP_COMMIT() asm volatile("cp.async.commit_group;")
#define CP_WAIT(n)  asm volatile("cp.async.wait_group %0;" :: "n"(n))

// ---------------- kernel A: precompute + zero counters ----------------
// blocks 0..45: pre tables; blocks 46..77: zero g_cnt
__global__ void __launch_bounds__(128) pre_kernel(
    const float* __restrict__ b1, const float* __restrict__ w2,
    const float* __restrict__ b2, const float* __restrict__ d1w)
{
    const int t = threadIdx.x;
    if (blockIdx.x >= 46) {
        int i = (blockIdx.x - 46) * 128 + t;
        if (i < 4096) g_cnt[i] = 0;
        return;
    }
    if (blockIdx.x == 0) {
        __shared__ float T[360];     // [tap][co]
        __shared__ float E[360];     // [cls][co], cls = yc*3+xc
        __shared__ float R[6][128];
        for (int item = t; item < 360; item += 128) {
            int tap = item / 40, co = item - 40 * tap;
            float s = 0.f;
            for (int ci = 0; ci < 40; ci++)
                s = fmaf(frelu(b1[ci]), w2[tap * 1600 + ci * 40 + co], s);
            T[item] = s;
        }
        __syncthreads();
        if (t < 40) {
            float s = b2[t];
            #pragma unroll
            for (int tap = 0; tap < 9; tap++) s += T[tap * 40 + t];
            g_c2[t] = s;
        }
        for (int item = t; item < 360; item += 128) {
            int cls = item / 40, co = item - 40 * cls;
            int yc = cls / 3, xc = cls - 3 * yc;
            float s = b2[co];
            #pragma unroll
            for (int tap = 0; tap < 9; tap++) {
                int dy = tap / 3, dx = tap % 3;
                bool vy = !((yc == 0 && dy == 0) || (yc == 2 && dy == 2));
                bool vx = !((xc == 0 && dx == 0) || (xc == 2 && dx == 2));
                if (vy && vx) s += T[tap * 40 + co];
            }
            E[item] = frelu(s);
        }
        __syncthreads();
        float loc[6] = {0.f, 0.f, 0.f, 0.f, 0.f, 0.f};
        for (int p = t; p < 256; p += 128) {
            int y = p >> 4, x = p & 15;
            if (y >= 2 && y <= 13 && x >= 2 && x <= 13) continue;
            int yc = (y == 0) ? 0 : (y == 15 ? 2 : 1);
            int xc = (x == 0) ? 0 : (x == 15 ? 2 : 1);
            const float* Ec = E + (yc * 3 + xc) * 40;
            for (int co = 0; co < 40; co++) {
                float v = Ec[co];
                const float* wr = d1w + (p * 40 + co) * 6;
                #pragma unroll
                for (int k = 0; k < 6; k++) loc[k] = fmaf(v, wr[k], loc[k]);
            }
        }
        #pragma unroll
        for (int k = 0; k < 6; k++) R[k][t] = loc[k];
        __syncthreads();
        if (t < 6) {
            float s = 0.f;
            for (int i = 0; i < 128; i++) s += R[t][i];
            g_extk[t] = s;
        }
    } else {
        int f = (blockIdx.x - 1) * 128 + t;   // 45 blocks * 128 = 5760
        int q = f / 40, co = f - 40 * q;
        int p = (2 + q / 12) * 16 + (2 + q % 12);
        const float* wr = d1w + (p * 40 + co) * 6;
        #pragma unroll
        for (int k2 = 0; k2 < 3; k2++)
            g_wint[k2 * 5760 + f] = make_float2(wr[2 * k2], wr[2 * k2 + 1]);
    }
}

// ---------------- kernel 1: patches + delta conv1/conv2 + dense1 ----------------
// grid 4096, block 128, 6 blocks/SM. smem (floats):
//   [0,3200)      w2b: conv2 weight double buffer (2 x 1600)
//   [1600,1924)   tok_s aliased INSIDE stage-1 (stage-1 first written at tap-0 top,
//                 after conv1 has consumed tok)
//   [3200,3216)   zero front guard
//   [3216,9024)   A: D planes [40][12x12] zero-ringed / act2 [144][40]; +zero tail guard
//   [9040,9400)   w1_s ; [9400,9440) b1_s ; [9440,9480) c2s ; [9480,9544) red_s
#define K1_SMEM_FLOATS 9544

__global__ void __launch_bounds__(128, 6) patch_kernel(
    const float* __restrict__ img, const float* __restrict__ lab,
    const float* __restrict__ msk,
    const float* __restrict__ w1, const float* __restrict__ b1,
    const float* __restrict__ w2, const float* __restrict__ d1b)
{
    extern __shared__ float smem[];
    float* w2b   = smem;
    float* tok_s = smem + 1600;
    float* A     = smem + 3216;
    float* w1_s  = smem + 9040;
    float* b1_s  = smem + 9400;
    float* c2s   = smem + 9440;
    float* red_s = smem + 9480;

    const int t = threadIdx.x;
    const int n = blockIdx.x;
    const int g = n >> 10;
    const int ij = n & 1023;
    const int i = ij >> 5, j = ij & 31;
    const int sx = g & 1, sy = g >> 1;
    const int r0 = 16 * i + 8 * sx - 4;
    const int c0 = 16 * j + 8 * sy - 4;
    const float cid = (float)((2 * i + sx) * 64 + (2 * j + sy));

    const uint32_t w2b_u = smem_u32(w2b);

    // prefetch conv2 tap-0 weights into stage 0
    #pragma unroll
    for (int r = 0; r < 4; ++r) {
        int k = t + 128 * r;
        if (k < 400) cp_async16(w2b_u + k * 16, (const float4*)w2 + k);
    }
    CP_COMMIT();

    for (int k = t; k < 360; k += 128) w1_s[k] = w1[k];
    if (t < 40) { b1_s[t] = b1[t]; c2s[t] = g_c2[t]; }
    for (int k = t; k < 324; k += 128) tok_s[k] = 0.f;
    // zero A + guards: floats [3200, 9040) relative to smem = 5840 = 1460 float4
    {
        float4* z = (float4*)(smem + 3200);
        #pragma unroll
        for (int r = 0; r < 12; ++r) {
            int k = t + 128 * r;
            if (k < 1460) z[k] = make_float4(0.f, 0.f, 0.f, 0.f);
        }
    }
    __syncthreads();

    // tokens + label sums
    float sum_f = 0.f, sum_lp = 0.f;
    #pragma unroll
    for (int pp = 0; pp < 2; ++pp) {
        int p = t + 128 * pp;
        int py = p >> 4, px = p & 15;
        int gr = r0 + py, gc = c0 + px;
        bool inb = (gr >= 0 && gr < 512 && gc >= 0 && gc < 512);
        float m = inb ? msk[gr * 512 + gc] : -1.f;
        float f = (m == cid) ? 1.f : 0.f;
        float iv = (inb ? img[gr * 512 + gc] : 0.f) * f;
        float lv = (inb ? lab[gr * 512 + gc] : 0.f) * f;
        tok_s[(py + 1) * 18 + px + 1] = iv;
        sum_f += f; sum_lp += lv;
    }
    #pragma unroll
    for (int o = 16; o; o >>= 1) {
        sum_f  += __shfl_down_sync(0xffffffffu, sum_f, o);
        sum_lp += __shfl_down_sync(0xffffffffu, sum_lp, o);
    }
    if ((t & 31) == 0) { red_s[(t >> 5) * 2] = sum_f; red_s[(t >> 5) * 2 + 1] = sum_lp; }
    __syncthreads();
    if (t == 0) {
        float sf = red_s[0] + red_s[2] + red_s[4] + red_s[6];
        float sl = red_s[1] + red_s[3] + red_s[5] + red_s[7];
        g_label[n] = dround(dround(sl / (sf + 1e-8f)));
    }

    // ---- conv1 delta on 10x10 (patch rows/cols 3..12) -> 12x12 zero-ringed planes ----
    if (t < 100) {
        int rr = 3 + t / 10, cc = 3 + t - 10 * (t / 10);
        float t9[9];
        #pragma unroll
        for (int k = 0; k < 9; k++) t9[k] = tok_s[(rr + k / 3) * 18 + (cc + k % 3)];
        int dpos = (rr - 2) * 12 + (cc - 2);    // interior of 12x12
        #pragma unroll 8
        for (int c = 0; c < 40; c++) {
            float s = 0.f;
            #pragma unroll
            for (int k = 0; k < 9; k++) s = fmaf(t9[k], w1_s[k * 40 + c], s);
            float b = b1_s[c];
            A[c * 144 + dpos] = frelu(b + s) - frelu(b);
        }
    }

    // ---- conv2 delta: 144 outputs (rows/cols 2..13), zero-ring addressing ----
    const int w = t >> 5, l = t & 31;

    unsigned long long acc[5][5];
    #pragma unroll
    for (int jj = 0; jj < 5; jj++)
        #pragma unroll
        for (int q2 = 0; q2 < 5; q2++) acc[jj][q2] = 0ull;

    for (int tap = 0; tap < 9; ++tap) {
        __syncthreads();      // prior readers of overwritten stage done (and conv1/tok at tap 0)
        if (tap < 8) {
            uint32_t dst = w2b_u + ((tap + 1) & 1) * 6400;
            const float4* src = (const float4*)(w2 + (tap + 1) * 1600);
            #pragma unroll
            for (int r = 0; r < 4; ++r) {
                int k = t + 128 * r;
                if (k < 400) cp_async16(dst + k * 16, src + k);
            }
            CP_COMMIT();
            CP_WAIT(1);
        } else {
            CP_WAIT(0);
        }
        __syncthreads();

        const int off = (tap / 3 - 1) * 12 + (tap % 3) - 1;   // in {-13..13}
        const float* wp = w2b + (tap & 1) * 1600 + 10 * w;
        const float* Dp = A + l + off;
        #pragma unroll 2
        for (int ci = 0; ci < 40; ++ci) {
            unsigned long long wv[5];
            #pragma unroll
            for (int q2 = 0; q2 < 5; q2++)
                wv[q2] = *(const unsigned long long*)(wp + 2 * q2);
            #pragma unroll
            for (int jj = 0; jj < 5; jj++) {
                float a = Dp[32 * jj];
                unsigned long long a2;
                asm("mov.b64 %0, {%1, %2};" : "=l"(a2) : "f"(a), "f"(a));
                #pragma unroll
                for (int q2 = 0; q2 < 5; q2++)
                    asm("fma.rn.f32x2 %0, %1, %2, %0;"
                        : "+l"(acc[jj][q2]) : "l"(a2), "l"(wv[q2]));
            }
            wp += 40; Dp += 144;
        }
    }
    __syncthreads();   // all D reads done; A may be overwritten

    // epilogue: act2 interior = relu(c2 + delta) -> A[q*40+co]
    #pragma unroll
    for (int jj = 0; jj < 5; jj++) {
        int q = 32 * jj + l;
        if (q < 144) {
            #pragma unroll
            for (int q2 = 0; q2 < 5; q2++) {
                float lo, hi;
                asm("mov.b64 {%0, %1}, %2;" : "=f"(lo), "=f"(hi) : "l"(acc[jj][q2]));
                int co = 10 * w + 2 * q2;
                float2 v = make_float2(frelu(lo + c2s[co]), frelu(hi + c2s[co + 1]));
                *(float2*)(A + q * 40 + co) = v;
            }
        }
    }
    __syncthreads();

    // ---- dense1 interior: 5760 elements, pre-gathered packed weights ----
    const unsigned long long* wt = (const unsigned long long*)g_wint;
    unsigned long long p3[3] = {0ull, 0ull, 0ull};
    for (int m = 0; m < 45; ++m) {
        int f = t + 128 * m;
        float v = A[f];
        unsigned long long a2;
        asm("mov.b64 %0, {%1, %2};" : "=l"(a2) : "f"(v), "f"(v));
        #pragma unroll
        for (int k2 = 0; k2 < 3; k2++) {
            unsigned long long wv = __ldg(wt + k2 * 5760 + f);
            asm("fma.rn.f32x2 %0, %1, %2, %0;" : "+l"(p3[k2]) : "l"(a2), "l"(wv));
        }
    }
    float part[6];
    #pragma unroll
    for (int k2 = 0; k2 < 3; k2++)
        asm("mov.b64 {%0, %1}, %2;" : "=f"(part[2 * k2]), "=f"(part[2 * k2 + 1]) : "l"(p3[k2]));
    #pragma unroll
    for (int k = 0; k < 6; k++)
        #pragma unroll
        for (int o = 16; o; o >>= 1) part[k] += __shfl_down_sync(0xffffffffu, part[k], o);
    if (l == 0) {
        #pragma unroll
        for (int k = 0; k < 6; k++) red_s[w * 6 + k] = part[k];
    }
    __syncthreads();
    if (t < 6) {
        float s = red_s[t] + red_s[6 + t] + red_s[12 + t] + red_s[18 + t];
        g_nodes[n * 6 + t] = frelu(s + g_extk[t] + d1b[t]);
    }
}

// ---------------- kernel 2: edge MLP + deterministic bucketing ----------------
__global__ void __launch_bounds__(128) edge_kernel(
    const int* __restrict__ snd, const int* __restrict__ rcv, int E,
    const float* __restrict__ we0, const float* __restrict__ be0,
    const float* __restrict__ we1, const float* __restrict__ be1,
    const float* __restrict__ we2, const float* __restrict__ be2,
    const float* __restrict__ we3, const float* __restrict__ be3)
{
    int e = blockIdx.x * 128 + threadIdx.x;
    if (e >= E) return;
    int s = snd[e], r = rcv[e];
    float x[13];
    #pragma unroll
    for (int k = 0; k < 6; k++) { x[k] = g_nodes[s * 6 + k]; x[6 + k] = g_nodes[r * 6 + k]; }
    x[12] = 1.f;

    float h0[5], h1[5], h2[5];
    #pragma unroll
    for (int k = 0; k < 5; k++) {
        float a = __ldg(be0 + k);
        #pragma unroll
        for (int i2 = 0; i2 < 13; i2++) a = fmaf(x[i2], __ldg(we0 + i2 * 5 + k), a);
        h0[k] = frelu(a);
    }
    #pragma unroll
    for (int k = 0; k < 5; k++) {
        float a = __ldg(be1 + k);
        #pragma unroll
        for (int i2 = 0; i2 < 5; i2++) a = fmaf(h0[i2], __ldg(we1 + i2 * 5 + k), a);
        h1[k] = frelu(a);
    }
    #pragma unroll
    for (int k = 0; k < 5; k++) {
        float a = __ldg(be2 + k);
        #pragma unroll
        for (int i2 = 0; i2 < 5; i2++) a = fmaf(h1[i2], __ldg(we2 + i2 * 5 + k), a);
        h2[k] = frelu(a);
    }
    #pragma unroll
    for (int k = 0; k < 10; k++) {
        float a = __ldg(be3 + k);
        #pragma unroll
        for (int i2 = 0; i2 < 5; i2++) a = fmaf(h2[i2], __ldg(we3 + i2 * 10 + k), a);
        g_efeat[e * 10 + k] = a;
    }
    int pos = atomicAdd(&g_cnt[r], 1);
    if (pos < 16) g_slot[r * 16 + pos] = e;
}

// ---------------- kernel 3: deterministic agg + node MLP + CE loss ----------------
__global__ void __launch_bounds__(32) node_kernel(
    const float* __restrict__ wn0, const float* __restrict__ bn0,
    const float* __restrict__ wn1, const float* __restrict__ bn1,
    const float* __restrict__ wn2, const float* __restrict__ bn2,
    const float* __restrict__ wn3, const float* __restrict__ bn3,
    const float* __restrict__ wout, const float* __restrict__ bout,
    float* __restrict__ out)
{
    int n = blockIdx.x * 32 + threadIdx.x;
    if (n >= 4096) return;

    int d = g_cnt[n]; if (d > 16) d = 16;
    int ids[16];
    for (int a = 0; a < d; a++) ids[a] = g_slot[n * 16 + a];
    for (int a = 1; a < d; a++) {
        int key = ids[a]; int b = a - 1;
        while (b >= 0 && ids[b] > key) { ids[b + 1] = ids[b]; b--; }
        ids[b + 1] = key;
    }
    float agg[10];
    #pragma unroll
    for (int k = 0; k < 10; k++) agg[k] = 0.f;
    for (int a = 0; a < d; a++) {
        int e = ids[a];
        #pragma unroll
        for (int k = 0; k < 10; k++) agg[k] += g_efeat[e * 10 + k];
    }

    float x[17];
    #pragma unroll
    for (int k = 0; k < 6; k++) x[k] = g_nodes[n * 6 + k];
    #pragma unroll
    for (int k = 0; k < 10; k++) x[6 + k] = agg[k];
    x[16] = 1.f;

    float h0[5], h1[5], h2[5], o[10];
    #pragma unroll
    for (int k = 0; k < 5; k++) {
        float a = __ldg(bn0 + k);
        #pragma unroll
        for (int i2 = 0; i2 < 17; i2++) a = fmaf(x[i2], __ldg(wn0 + i2 * 5 + k), a);
        h0[k] = frelu(a);
    }
    #pragma unroll
    for (int k = 0; k < 5; k++) {
        float a = __ldg(bn1 + k);
        #pragma unroll
        for (int i2 = 0; i2 < 5; i2++) a = fmaf(h0[i2], __ldg(wn1 + i2 * 5 + k), a);
        h1[k] = frelu(a);
    }
    #pragma unroll
    for (int k = 0; k < 5; k++) {
        float a = __ldg(bn2 + k);
        #pragma unroll
        for (int i2 = 0; i2 < 5; i2++) a = fmaf(h1[i2], __ldg(wn2 + i2 * 5 + k), a);
        h2[k] = frelu(a);
    }
    #pragma unroll
    for (int k = 0; k < 10; k++) {
        float a = __ldg(bn3 + k);
        #pragma unroll
        for (int i2 = 0; i2 < 5; i2++) a = fmaf(h2[i2], __ldg(wn3 + i2 * 10 + k), a);
        o[k] = a;
    }
    float l0 = __ldg(bout + 0), l1 = __ldg(bout + 1);
    #pragma unroll
    for (int i2 = 0; i2 < 10; i2++) {
        l0 = fmaf(o[i2], __ldg(wout + i2 * 2 + 0), l0);
        l1 = fmaf(o[i2], __ldg(wout + i2 * 2 + 1), l1);
    }
    float m = fmaxf(l0, l1);
    float lse = m + logf(expf(l0 - m) + expf(l1 - m));
    float sv = g_label[n];
    out[n] = -((1.f - sv) * (l0 - lse) + sv * (l1 - lse));
}

// ---------------- launch ----------------
extern "C" void kernel_launch(void* const* d_in, const int* in_sizes, int n_in,
                              void* d_out, int out_size)
{
    const float* img = (const float*)d_in[0];
    const float* lab = (const float*)d_in[1];
    const float* msk = (const float*)d_in[2];
    const float* w1  = (const float*)d_in[3];
    const float* b1  = (const float*)d_in[4];
    const float* w2  = (const float*)d_in[5];
    const float* b2  = (const float*)d_in[6];
    const float* d1w = (const float*)d_in[7];
    const float* d1b = (const float*)d_in[8];
    const float* we0 = (const float*)d_in[9];
    const float* be0 = (const float*)d_in[10];
    const float* we1 = (const float*)d_in[11];
    const float* be1 = (const float*)d_in[12];
    const float* we2 = (const float*)d_in[13];
    const float* be2 = (const float*)d_in[14];
    const float* we3 = (const float*)d_in[15];
    const float* be3 = (const float*)d_in[16];
    const float* wn0 = (const float*)d_in[17];
    const float* bn0 = (const float*)d_in[18];
    const float* wn1 = (const float*)d_in[19];
    const float* bn1 = (const float*)d_in[20];
    const float* wn2 = (const float*)d_in[21];
    const float* bn2 = (const float*)d_in[22];
    const float* wn3 = (const float*)d_in[23];
    const float* bn3 = (const float*)d_in[24];
    const float* wout = (const float*)d_in[25];
    const float* bout = (const float*)d_in[26];
    const int* snd = (const int*)d_in[27];
    const int* rcv = (const int*)d_in[28];
    int E = in_sizes[27];

    int smem_bytes = K1_SMEM_FLOATS * (int)sizeof(float);
    static int configured = -1;
    if (configured != smem_bytes) {
        cudaFuncSetAttribute(patch_kernel, cudaFuncAttributeMaxDynamicSharedMemorySize, smem_bytes);
        configured = smem_bytes;
    }

    pre_kernel<<<78, 128>>>(b1, w2, b2, d1w);
    patch_kernel<<<4096, 128, smem_bytes>>>(img, lab, msk, w1, b1, w2, d1b);
    edge_kernel<<<(E + 127) / 128, 128>>>(snd, rcv, E, we0, be0, we1, be1, we2, be2, we3, be3);
    node_kernel<<<128, 32>>>(wn0, bn0, wn1, bn1, wn2, bn2, wn3, bn3, wout, bout, (float*)d_out);

    (void)n_in; (void)out_size;
}

// round 5
// speedup vs baseline: 4.1576x; 2.3877x over previous
#include <cuda_runtime.h>
#include <math.h>
#include <stdint.h>

#define TWO_PI_F 6.2831853071795864769f

// ---------------- scratch ----------------
__device__ float g_nodes[4096 * 6];
__device__ float g_label[4096];
__device__ float g_efeat[16128 * 10];
__device__ int   g_slot[4096 * 16];
__device__ int   g_cnt[4096];
// per-launch precompute
__device__ float g_c2[40];                 // b2 + sum_taps T  (interior base)
__device__ float g_extk[6];                // exterior pixels' dense1 contribution
__device__ float2 g_wint[3 * 5760];        // interior dense1 weights [k-pair][f]
__device__ float g_w2t[14400];             // conv2 weights, tf32-rounded

__device__ __forceinline__ float frelu(float x) { return x > 0.f ? x : 0.f; }
__device__ __forceinline__ float dround(float x) {
    return x - sinf(x * TWO_PI_F) * (1.0f / TWO_PI_F);
}
__device__ __forceinline__ float to_tf32(float x) {
    float r; asm("cvt.rna.tf32.f32 %0, %1;" : "=f"(r) : "f"(x)); return r;
}
__device__ __forceinline__ uint32_t smem_u32(const void* p) {
    uint32_t a;
    asm("{ .reg .u64 t; cvta.to.shared.u64 t, %1; cvt.u32.u64 %0, t; }" : "=r"(a) : "l"(p));
    return a;
}
__device__ __forceinline__ void cp_async16(uint32_t dst, const void* src) {
    asm volatile("cp.async.cg.shared.global [%0], [%1], 16;" :: "r"(dst), "l"(src));
}
#define CP_COMMIT() asm volatile("cp.async.commit_group;")
#define CP_WAIT(n)  asm volatile("cp.async.wait_group %0;" :: "n"(n))

// ---------------- kernel A: precompute + zero counters + tf32 weights ----------------
// block 0: tables; 1..45: g_wint; 46..77: zero g_cnt; 78..190: g_w2t
__global__ void __launch_bounds__(128) pre_kernel(
    const float* __restrict__ b1, const float* __restrict__ w2,
    const float* __restrict__ b2, const float* __restrict__ d1w)
{
    const int t = threadIdx.x;
    if (blockIdx.x >= 78) {
        int idx = (blockIdx.x - 78) * 128 + t;
        if (idx < 14400) g_w2t[idx] = to_tf32(w2[idx]);
        return;
    }
    if (blockIdx.x >= 46) {
        int i = (blockIdx.x - 46) * 128 + t;
        if (i < 4096) g_cnt[i] = 0;
        return;
    }
    if (blockIdx.x == 0) {
        __shared__ float T[360];     // [tap][co]
        __shared__ float E[360];     // [cls][co], cls = yc*3+xc
        __shared__ float R[6][128];
        for (int item = t; item < 360; item += 128) {
            int tap = item / 40, co = item - 40 * tap;
            float s = 0.f;
            for (int ci = 0; ci < 40; ci++)
                s = fmaf(frelu(b1[ci]), w2[tap * 1600 + ci * 40 + co], s);
            T[item] = s;
        }
        __syncthreads();
        if (t < 40) {
            float s = b2[t];
            #pragma unroll
            for (int tap = 0; tap < 9; tap++) s += T[tap * 40 + t];
            g_c2[t] = s;
        }
        for (int item = t; item < 360; item += 128) {
            int cls = item / 40, co = item - 40 * cls;
            int yc = cls / 3, xc = cls - 3 * yc;
            float s = b2[co];
            #pragma unroll
            for (int tap = 0; tap < 9; tap++) {
                int dy = tap / 3, dx = tap % 3;
                bool vy = !((yc == 0 && dy == 0) || (yc == 2 && dy == 2));
                bool vx = !((xc == 0 && dx == 0) || (xc == 2 && dx == 2));
                if (vy && vx) s += T[tap * 40 + co];
            }
            E[item] = frelu(s);
        }
        __syncthreads();
        float loc[6] = {0.f, 0.f, 0.f, 0.f, 0.f, 0.f};
        for (int p = t; p < 256; p += 128) {
            int y = p >> 4, x = p & 15;
            if (y >= 2 && y <= 13 && x >= 2 && x <= 13) continue;
            int yc = (y == 0) ? 0 : (y == 15 ? 2 : 1);
            int xc = (x == 0) ? 0 : (x == 15 ? 2 : 1);
            const float* Ec = E + (yc * 3 + xc) * 40;
            for (int co = 0; co < 40; co++) {
                float v = Ec[co];
                const float* wr = d1w + (p * 40 + co) * 6;
                #pragma unroll
                for (int k = 0; k < 6; k++) loc[k] = fmaf(v, wr[k], loc[k]);
            }
        }
        #pragma unroll
        for (int k = 0; k < 6; k++) R[k][t] = loc[k];
        __syncthreads();
        if (t < 6) {
            float s = 0.f;
            for (int i = 0; i < 128; i++) s += R[t][i];
            g_extk[t] = s;
        }
    } else {
        int f = (blockIdx.x - 1) * 128 + t;   // 45 blocks * 128 = 5760
        int q = f / 40, co = f - 40 * q;
        int p = (2 + q / 12) * 16 + (2 + q % 12);
        const float* wr = d1w + (p * 40 + co) * 6;
        #pragma unroll
        for (int k2 = 0; k2 < 3; k2++)
            g_wint[k2 * 5760 + f] = make_float2(wr[2 * k2], wr[2 * k2 + 1]);
    }
}

// ---------------- kernel 1: patches + delta conv1 + tf32-MMA conv2 + dense1 ----------------
// grid 4096, block 128. smem (floats):
//   [0,3200)      w2b: conv2 tf32 weight double buffer (2 x 1600)
//   [1600,1924)   tok_s aliased inside stage-1 (first written at tap-0 top, after conv1)
//   [3203,3216)   zero front guard (13)
//   [3216,9296)   Dg: D planes [40][152] zero-ringed / act2 [144][40]
//   [9296,9301)   zero tail guard (5)
//   [9304,9664)   w1_s ; [9664,9704) b1_s ; [9704,9744) c2s ; [9744,9808) red_s
#define K1_SMEM_FLOATS 9808

// tf32 m16n8k8: lane = 4*g2 + tg ; A row-major frag, B col-major frag
#define MMA_TILE(Ap, CB, NTLO, NTHI) do {                                     \
    uint32_t a0 = __float_as_uint((Ap)[tg152]);                               \
    uint32_t a1 = __float_as_uint((Ap)[tg152 + 8]);                           \
    uint32_t a2 = __float_as_uint((Ap)[tg152 + 608]);                         \
    uint32_t a3 = __float_as_uint((Ap)[tg152 + 616]);                         \
    _Pragma("unroll")                                                         \
    for (int nt = (NTLO); nt < (NTHI); ++nt) {                                \
        float* c = C[(CB) + nt - (NTLO)];                                     \
        asm("mma.sync.aligned.m16n8k8.row.col.f32.tf32.tf32.f32 "             \
            "{%0,%1,%2,%3}, {%4,%5,%6,%7}, {%8,%9}, {%0,%1,%2,%3};"           \
            : "+f"(c[0]), "+f"(c[1]), "+f"(c[2]), "+f"(c[3])                  \
            : "r"(a0), "r"(a1), "r"(a2), "r"(a3), "r"(B0[nt]), "r"(B1[nt]));  \
    }                                                                         \
} while (0)

#define KSTEPS(MT0, L0, H0, C0, MT1, L1, H1, C1, MT2, L2, H2, C2) do {        \
    _Pragma("unroll")                                                         \
    for (int s = 0; s < 5; ++s) {                                             \
        const float* wk = wb + (8 * s + tg) * 40 + g2;                        \
        uint32_t B0[5], B1[5];                                                \
        _Pragma("unroll")                                                     \
        for (int nt = 0; nt < 5; ++nt) {                                      \
            B0[nt] = __float_as_uint(wk[8 * nt]);                             \
            B1[nt] = __float_as_uint(wk[160 + 8 * nt]);                       \
        }                                                                     \
        const float* As = Db + s * 1216 + g2;                                 \
        MMA_TILE(As + 16 * (MT0), C0, L0, H0);                                \
        MMA_TILE(As + 16 * (MT1), C1, L1, H1);                                \
        MMA_TILE(As + 16 * (MT2), C2, L2, H2);                                \
    }                                                                         \
} while (0)

#define EPI_TILE(MT, NTLO, NTHI, CB) do {                                     \
    _Pragma("unroll")                                                         \
    for (int nt = (NTLO); nt < (NTHI); ++nt) {                                \
        float* c = C[(CB) + nt - (NTLO)];                                     \
        int px0 = 16 * (MT) + g2;                                             \
        int co = 8 * nt + 2 * tg;                                             \
        *(float2*)(act2 + px0 * 40 + co) =                                    \
            make_float2(frelu(c2s[co] + c[0]), frelu(c2s[co + 1] + c[1]));    \
        *(float2*)(act2 + (px0 + 8) * 40 + co) =                              \
            make_float2(frelu(c2s[co] + c[2]), frelu(c2s[co + 1] + c[3]));    \
    }                                                                         \
} while (0)

__global__ void __launch_bounds__(128, 5) patch_kernel(
    const float* __restrict__ img, const float* __restrict__ lab,
    const float* __restrict__ msk,
    const float* __restrict__ w1, const float* __restrict__ b1,
    const float* __restrict__ d1b)
{
    extern __shared__ float smem[];
    float* w2b   = smem;
    float* tok_s = smem + 1600;
    float* Dg    = smem + 3216;
    float* w1_s  = smem + 9304;
    float* b1_s  = smem + 9664;
    float* c2s   = smem + 9704;
    float* red_s = smem + 9744;

    const int t = threadIdx.x;
    const int n = blockIdx.x;
    const int g = n >> 10;
    const int ij = n & 1023;
    const int i = ij >> 5, j = ij & 31;
    const int sx = g & 1, sy = g >> 1;
    const int r0 = 16 * i + 8 * sx - 4;
    const int c0 = 16 * j + 8 * sy - 4;
    const float cid = (float)((2 * i + sx) * 64 + (2 * j + sy));

    const uint32_t w2b_u = smem_u32(w2b);

    // prefetch conv2 tap-0 tf32 weights into stage 0
    #pragma unroll
    for (int r = 0; r < 4; ++r) {
        int k = t + 128 * r;
        if (k < 400) cp_async16(w2b_u + k * 16, (const float4*)g_w2t + k);
    }
    CP_COMMIT();

    for (int k = t; k < 360; k += 128) w1_s[k] = w1[k];
    if (t < 40) { b1_s[t] = b1[t]; c2s[t] = g_c2[t]; }
    for (int k = t; k < 324; k += 128) tok_s[k] = 0.f;
    // zero D + guards: floats [3200, 9304) = 6104 = 1526 float4
    {
        float4* z = (float4*)(smem + 3200);
        #pragma unroll
        for (int r = 0; r < 12; ++r) {
            int k = t + 128 * r;
            if (k < 1526) z[k] = make_float4(0.f, 0.f, 0.f, 0.f);
        }
    }
    __syncthreads();

    // tokens + label sums
    float sum_f = 0.f, sum_lp = 0.f;
    #pragma unroll
    for (int pp = 0; pp < 2; ++pp) {
        int p = t + 128 * pp;
        int py = p >> 4, px = p & 15;
        int gr = r0 + py, gc = c0 + px;
        bool inb = (gr >= 0 && gr < 512 && gc >= 0 && gc < 512);
        float m = inb ? msk[gr * 512 + gc] : -1.f;
        float f = (m == cid) ? 1.f : 0.f;
        float iv = (inb ? img[gr * 512 + gc] : 0.f) * f;
        float lv = (inb ? lab[gr * 512 + gc] : 0.f) * f;
        tok_s[(py + 1) * 18 + px + 1] = iv;
        sum_f += f; sum_lp += lv;
    }
    #pragma unroll
    for (int o = 16; o; o >>= 1) {
        sum_f  += __shfl_down_sync(0xffffffffu, sum_f, o);
        sum_lp += __shfl_down_sync(0xffffffffu, sum_lp, o);
    }
    if ((t & 31) == 0) { red_s[(t >> 5) * 2] = sum_f; red_s[(t >> 5) * 2 + 1] = sum_lp; }
    __syncthreads();
    if (t == 0) {
        float sf = red_s[0] + red_s[2] + red_s[4] + red_s[6];
        float sl = red_s[1] + red_s[3] + red_s[5] + red_s[7];
        g_label[n] = dround(dround(sl / (sf + 1e-8f)));
    }

    // ---- conv1 delta on 10x10 -> 12x12 zero-ringed planes (stride 152), tf32-rounded ----
    if (t < 100) {
        int rr = 3 + t / 10, cc = 3 + t - 10 * (t / 10);
        float t9[9];
        #pragma unroll
        for (int k = 0; k < 9; k++) t9[k] = tok_s[(rr + k / 3) * 18 + (cc + k % 3)];
        int dpos = (rr - 2) * 12 + (cc - 2);
        #pragma unroll 8
        for (int c = 0; c < 40; c++) {
            float s = 0.f;
            #pragma unroll
            for (int k = 0; k < 9; k++) s = fmaf(t9[k], w1_s[k * 40 + c], s);
            float b = b1_s[c];
            Dg[c * 152 + dpos] = to_tf32(frelu(b + s) - frelu(b));
        }
    }

    // ---- conv2 delta via tf32 mma: 9 Mtiles x 5 Ntiles, warp split {12,11,11,11} ----
    const int w = t >> 5, l = t & 31;
    const int g2 = l >> 2, tg = l & 3;
    const int tg152 = tg * 152;

    float C[12][4];
    #pragma unroll
    for (int a = 0; a < 12; a++)
        #pragma unroll
        for (int b = 0; b < 4; b++) C[a][b] = 0.f;

    for (int tap = 0; tap < 9; ++tap) {
        __syncthreads();      // prior readers of overwritten stage done (conv1/tok at tap 0)
        if (tap < 8) {
            uint32_t dst = w2b_u + ((tap + 1) & 1) * 6400;
            const float4* src = (const float4*)(g_w2t + (tap + 1) * 1600);
            #pragma unroll
            for (int r = 0; r < 4; ++r) {
                int k = t + 128 * r;
                if (k < 400) cp_async16(dst + k * 16, src + k);
            }
            CP_COMMIT();
            CP_WAIT(1);
        } else {
            CP_WAIT(0);
        }
        __syncthreads();

        const int off = (tap / 3 - 1) * 12 + (tap % 3) - 1;
        const float* wb = w2b + (tap & 1) * 1600;
        const float* Db = Dg + off;

        if (w == 0) {
            KSTEPS(0, 0, 5, 0,   1, 0, 5, 5,   2, 0, 2, 10);
        } else if (w == 1) {
            KSTEPS(2, 2, 5, 0,   3, 0, 5, 3,   4, 0, 3, 8);
        } else if (w == 2) {
            KSTEPS(4, 3, 5, 0,   5, 0, 5, 2,   6, 0, 4, 7);
        } else {
            KSTEPS(6, 4, 5, 0,   7, 0, 5, 1,   8, 0, 5, 6);
        }
    }
    __syncthreads();   // all D reads done; Dg may be overwritten

    // epilogue: act2 = relu(c2 + delta) -> act2[q*40+co]
    float* act2 = Dg;
    if (w == 0) {
        EPI_TILE(0, 0, 5, 0); EPI_TILE(1, 0, 5, 5); EPI_TILE(2, 0, 2, 10);
    } else if (w == 1) {
        EPI_TILE(2, 2, 5, 0); EPI_TILE(3, 0, 5, 3); EPI_TILE(4, 0, 3, 8);
    } else if (w == 2) {
        EPI_TILE(4, 3, 5, 0); EPI_TILE(5, 0, 5, 2); EPI_TILE(6, 0, 4, 7);
    } else {
        EPI_TILE(6, 4, 5, 0); EPI_TILE(7, 0, 5, 1); EPI_TILE(8, 0, 5, 6);
    }
    __syncthreads();

    // ---- dense1 interior: 5760 elements, pre-gathered packed weights ----
    const unsigned long long* wt = (const unsigned long long*)g_wint;
    unsigned long long p3[3] = {0ull, 0ull, 0ull};
    for (int m = 0; m < 45; ++m) {
        int f = t + 128 * m;
        float v = act2[f];
        unsigned long long a2;
        asm("mov.b64 %0, {%1, %2};" : "=l"(a2) : "f"(v), "f"(v));
        #pragma unroll
        for (int k2 = 0; k2 < 3; k2++) {
            unsigned long long wv = __ldg(wt + k2 * 5760 + f);
            asm("fma.rn.f32x2 %0, %1, %2, %0;" : "+l"(p3[k2]) : "l"(a2), "l"(wv));
        }
    }
    float part[6];
    #pragma unroll
    for (int k2 = 0; k2 < 3; k2++)
        asm("mov.b64 {%0, %1}, %2;" : "=f"(part[2 * k2]), "=f"(part[2 * k2 + 1]) : "l"(p3[k2]));
    #pragma unroll
    for (int k = 0; k < 6; k++)
        #pragma unroll
        for (int o = 16; o; o >>= 1) part[k] += __shfl_down_sync(0xffffffffu, part[k], o);
    if (l == 0) {
        #pragma unroll
        for (int k = 0; k < 6; k++) red_s[w * 6 + k] = part[k];
    }
    __syncthreads();
    if (t < 6) {
        float s = red_s[t] + red_s[6 + t] + red_s[12 + t] + red_s[18 + t];
        g_nodes[n * 6 + t] = frelu(s + g_extk[t] + d1b[t]);
    }
}

// ---------------- kernel 2: edge MLP + deterministic bucketing ----------------
__global__ void __launch_bounds__(128) edge_kernel(
    const int* __restrict__ snd, const int* __restrict__ rcv, int E,
    const float* __restrict__ we0, const float* __restrict__ be0,
    const float* __restrict__ we1, const float* __restrict__ be1,
    const float* __restrict__ we2, const float* __restrict__ be2,
    const float* __restrict__ we3, const float* __restrict__ be3)
{
    int e = blockIdx.x * 128 + threadIdx.x;
    if (e >= E) return;
    int s = snd[e], r = rcv[e];
    float x[13];
    #pragma unroll
    for (int k = 0; k < 6; k++) { x[k] = g_nodes[s * 6 + k]; x[6 + k] = g_nodes[r * 6 + k]; }
    x[12] = 1.f;

    float h0[5], h1[5], h2[5];
    #pragma unroll
    for (int k = 0; k < 5; k++) {
        float a = __ldg(be0 + k);
        #pragma unroll
        for (int i2 = 0; i2 < 13; i2++) a = fmaf(x[i2], __ldg(we0 + i2 * 5 + k), a);
        h0[k] = frelu(a);
    }
    #pragma unroll
    for (int k = 0; k < 5; k++) {
        float a = __ldg(be1 + k);
        #pragma unroll
        for (int i2 = 0; i2 < 5; i2++) a = fmaf(h0[i2], __ldg(we1 + i2 * 5 + k), a);
        h1[k] = frelu(a);
    }
    #pragma unroll
    for (int k = 0; k < 5; k++) {
        float a = __ldg(be2 + k);
        #pragma unroll
        for (int i2 = 0; i2 < 5; i2++) a = fmaf(h1[i2], __ldg(we2 + i2 * 5 + k), a);
        h2[k] = frelu(a);
    }
    #pragma unroll
    for (int k = 0; k < 10; k++) {
        float a = __ldg(be3 + k);
        #pragma unroll
        for (int i2 = 0; i2 < 5; i2++) a = fmaf(h2[i2], __ldg(we3 + i2 * 10 + k), a);
        g_efeat[e * 10 + k] = a;
    }
    int pos = atomicAdd(&g_cnt[r], 1);
    if (pos < 16) g_slot[r * 16 + pos] = e;
}

// ---------------- kernel 3: deterministic agg + node MLP + CE loss ----------------
__global__ void __launch_bounds__(32) node_kernel(
    const float* __restrict__ wn0, const float* __restrict__ bn0,
    const float* __restrict__ wn1, const float* __restrict__ bn1,
    const float* __restrict__ wn2, const float* __restrict__ bn2,
    const float* __restrict__ wn3, const float* __restrict__ bn3,
    const float* __restrict__ wout, const float* __restrict__ bout,
    float* __restrict__ out)
{
    int n = blockIdx.x * 32 + threadIdx.x;
    if (n >= 4096) return;

    int d = g_cnt[n]; if (d > 16) d = 16;
    int ids[16];
    for (int a = 0; a < d; a++) ids[a] = g_slot[n * 16 + a];
    for (int a = 1; a < d; a++) {
        int key = ids[a]; int b = a - 1;
        while (b >= 0 && ids[b] > key) { ids[b + 1] = ids[b]; b--; }
        ids[b + 1] = key;
    }
    float agg[10];
    #pragma unroll
    for (int k = 0; k < 10; k++) agg[k] = 0.f;
    for (int a = 0; a < d; a++) {
        int e = ids[a];
        #pragma unroll
        for (int k = 0; k < 10; k++) agg[k] += g_efeat[e * 10 + k];
    }

    float x[17];
    #pragma unroll
    for (int k = 0; k < 6; k++) x[k] = g_nodes[n * 6 + k];
    #pragma unroll
    for (int k = 0; k < 10; k++) x[6 + k] = agg[k];
    x[16] = 1.f;

    float h0[5], h1[5], h2[5], o[10];
    #pragma unroll
    for (int k = 0; k < 5; k++) {
        float a = __ldg(bn0 + k);
        #pragma unroll
        for (int i2 = 0; i2 < 17; i2++) a = fmaf(x[i2], __ldg(wn0 + i2 * 5 + k), a);
        h0[k] = frelu(a);
    }
    #pragma unroll
    for (int k = 0; k < 5; k++) {
        float a = __ldg(bn1 + k);
        #pragma unroll
        for (int i2 = 0; i2 < 5; i2++) a = fmaf(h0[i2], __ldg(wn1 + i2 * 5 + k), a);
        h1[k] = frelu(a);
    }
    #pragma unroll
    for (int k = 0; k < 5; k++) {
        float a = __ldg(bn2 + k);
        #pragma unroll
        for (int i2 = 0; i2 < 5; i2++) a = fmaf(h1[i2], __ldg(wn2 + i2 * 5 + k), a);
        h2[k] = frelu(a);
    }
    #pragma unroll
    for (int k = 0; k < 10; k++) {
        float a = __ldg(bn3 + k);
        #pragma unroll
        for (int i2 = 0; i2 < 5; i2++) a = fmaf(h2[i2], __ldg(wn3 + i2 * 10 + k), a);
        o[k] = a;
    }
    float l0 = __ldg(bout + 0), l1 = __ldg(bout + 1);
    #pragma unroll
    for (int i2 = 0; i2 < 10; i2++) {
        l0 = fmaf(o[i2], __ldg(wout + i2 * 2 + 0), l0);
        l1 = fmaf(o[i2], __ldg(wout + i2 * 2 + 1), l1);
    }
    float m = fmaxf(l0, l1);
    float lse = m + logf(expf(l0 - m) + expf(l1 - m));
    float sv = g_label[n];
    out[n] = -((1.f - sv) * (l0 - lse) + sv * (l1 - lse));
}

// ---------------- launch ----------------
extern "C" void kernel_launch(void* const* d_in, const int* in_sizes, int n_in,
                              void* d_out, int out_size)
{
    const float* img = (const float*)d_in[0];
    const float* lab = (const float*)d_in[1];
    const float* msk = (const float*)d_in[2];
    const float* w1  = (const float*)d_in[3];
    const float* b1  = (const float*)d_in[4];
    const float* w2  = (const float*)d_in[5];
    const float* b2  = (const float*)d_in[6];
    const float* d1w = (const float*)d_in[7];
    const float* d1b = (const float*)d_in[8];
    const float* we0 = (const float*)d_in[9];
    const float* be0 = (const float*)d_in[10];
    const float* we1 = (const float*)d_in[11];
    const float* be1 = (const float*)d_in[12];
    const float* we2 = (const float*)d_in[13];
    const float* be2 = (const float*)d_in[14];
    const float* we3 = (const float*)d_in[15];
    const float* be3 = (const float*)d_in[16];
    const float* wn0 = (const float*)d_in[17];
    const float* bn0 = (const float*)d_in[18];
    const float* wn1 = (const float*)d_in[19];
    const float* bn1 = (const float*)d_in[20];
    const float* wn2 = (const float*)d_in[21];
    const float* bn2 = (const float*)d_in[22];
    const float* wn3 = (const float*)d_in[23];
    const float* bn3 = (const float*)d_in[24];
    const float* wout = (const float*)d_in[25];
    const float* bout = (const float*)d_in[26];
    const int* snd = (const int*)d_in[27];
    const int* rcv = (const int*)d_in[28];
    int E = in_sizes[27];

    int smem_bytes = K1_SMEM_FLOATS * (int)sizeof(float);
    static int configured = -1;
    if (configured != smem_bytes) {
        cudaFuncSetAttribute(patch_kernel, cudaFuncAttributeMaxDynamicSharedMemorySize, smem_bytes);
        configured = smem_bytes;
    }

    pre_kernel<<<191, 128>>>(b1, w2, b2, d1w);
    patch_kernel<<<4096, 128, smem_bytes>>>(img, lab, msk, w1, b1, d1b);
    edge_kernel<<<(E + 127) / 128, 128>>>(snd, rcv, E, we0, be0, we1, be1, we2, be2, we3, be3);
    node_kernel<<<128, 32>>>(wn0, bn0, wn1, bn1, wn2, bn2, wn3, bn3, wout, bout, (float*)d_out);

    (void)n_in; (void)out_size;
}

// round 6
// speedup vs baseline: 4.1927x; 1.0084x over previous
#include <cuda_runtime.h>
#include <math.h>
#include <stdint.h>

#define TWO_PI_F 6.2831853071795864769f

// ---------------- scratch ----------------
__device__ float g_nodes[4096 * 6];
__device__ float g_label[4096];
__device__ float g_efeat[16128 * 12];      // padded to 12 floats/edge (16B aligned)
__device__ int   g_slot[4096 * 16];
__device__ int   g_cnt[4096];
// per-launch precompute
__device__ float g_c2[40];
__device__ float g_extk[6];
__device__ float2 g_wint[3 * 5760];
__device__ float g_w2t[14400];             // conv2 weights, tf32-rounded

__device__ __forceinline__ float frelu(float x) { return x > 0.f ? x : 0.f; }
__device__ __forceinline__ float dround(float x) {
    return x - sinf(x * TWO_PI_F) * (1.0f / TWO_PI_F);
}
__device__ __forceinline__ float to_tf32(float x) {
    float r; asm("cvt.rna.tf32.f32 %0, %1;" : "=f"(r) : "f"(x)); return r;
}
__device__ __forceinline__ uint32_t smem_u32(const void* p) {
    uint32_t a;
    asm("{ .reg .u64 t; cvta.to.shared.u64 t, %1; cvt.u32.u64 %0, t; }" : "=r"(a) : "l"(p));
    return a;
}
__device__ __forceinline__ void cp_async16(uint32_t dst, const void* src) {
    asm volatile("cp.async.cg.shared.global [%0], [%1], 16;" :: "r"(dst), "l"(src));
}
#define CP_COMMIT() asm volatile("cp.async.commit_group;")
#define CP_WAIT(n)  asm volatile("cp.async.wait_group %0;" :: "n"(n))

// ---------------- kernel A: precompute + zero counters + tf32 weights ----------------
__global__ void __launch_bounds__(128) pre_kernel(
    const float* __restrict__ b1, const float* __restrict__ w2,
    const float* __restrict__ b2, const float* __restrict__ d1w)
{
    const int t = threadIdx.x;
    if (blockIdx.x >= 78) {
        int idx = (blockIdx.x - 78) * 128 + t;
        if (idx < 14400) g_w2t[idx] = to_tf32(w2[idx]);
        return;
    }
    if (blockIdx.x >= 46) {
        int i = (blockIdx.x - 46) * 128 + t;
        if (i < 4096) g_cnt[i] = 0;
        return;
    }
    if (blockIdx.x == 0) {
        __shared__ float T[360];
        __shared__ float E[360];
        __shared__ float R[6][128];
        for (int item = t; item < 360; item += 128) {
            int tap = item / 40, co = item - 40 * tap;
            float s = 0.f;
            for (int ci = 0; ci < 40; ci++)
                s = fmaf(frelu(b1[ci]), w2[tap * 1600 + ci * 40 + co], s);
            T[item] = s;
        }
        __syncthreads();
        if (t < 40) {
            float s = b2[t];
            #pragma unroll
            for (int tap = 0; tap < 9; tap++) s += T[tap * 40 + t];
            g_c2[t] = s;
        }
        for (int item = t; item < 360; item += 128) {
            int cls = item / 40, co = item - 40 * cls;
            int yc = cls / 3, xc = cls - 3 * yc;
            float s = b2[co];
            #pragma unroll
            for (int tap = 0; tap < 9; tap++) {
                int dy = tap / 3, dx = tap % 3;
                bool vy = !((yc == 0 && dy == 0) || (yc == 2 && dy == 2));
                bool vx = !((xc == 0 && dx == 0) || (xc == 2 && dx == 2));
                if (vy && vx) s += T[tap * 40 + co];
            }
            E[item] = frelu(s);
        }
        __syncthreads();
        float loc[6] = {0.f, 0.f, 0.f, 0.f, 0.f, 0.f};
        for (int p = t; p < 256; p += 128) {
            int y = p >> 4, x = p & 15;
            if (y >= 2 && y <= 13 && x >= 2 && x <= 13) continue;
            int yc = (y == 0) ? 0 : (y == 15 ? 2 : 1);
            int xc = (x == 0) ? 0 : (x == 15 ? 2 : 1);
            const float* Ec = E + (yc * 3 + xc) * 40;
            for (int co = 0; co < 40; co++) {
                float v = Ec[co];
                const float* wr = d1w + (p * 40 + co) * 6;
                #pragma unroll
                for (int k = 0; k < 6; k++) loc[k] = fmaf(v, wr[k], loc[k]);
            }
        }
        #pragma unroll
        for (int k = 0; k < 6; k++) R[k][t] = loc[k];
        __syncthreads();
        if (t < 6) {
            float s = 0.f;
            for (int i = 0; i < 128; i++) s += R[t][i];
            g_extk[t] = s;
        }
    } else {
        int f = (blockIdx.x - 1) * 128 + t;
        int q = f / 40, co = f - 40 * q;
        int p = (2 + q / 12) * 16 + (2 + q % 12);
        const float* wr = d1w + (p * 40 + co) * 6;
        #pragma unroll
        for (int k2 = 0; k2 < 3; k2++)
            g_wint[k2 * 5760 + f] = make_float2(wr[2 * k2], wr[2 * k2 + 1]);
    }
}

// ---------------- kernel 1: dual-patch blocks ----------------
// grid 2048, block 256 (warpgroup wg=t>>7 owns patch 2*bid+wg). smem (floats):
//   [0,3200)        w2b double buffer (2 x 1600)
//   [1600,1948)     tok0 / [1948,2272) tok1 (aliased in stage-1; consumed before tap0 prefetch)
//   [3200,3216)     zero front guard 0
//   [3216,9296)     Dg0 (40 planes stride 152) ; [9296,9312) guards
//   [9312,15392)    Dg1 ; [15392,15408) tail guard
//   [15408,15768)   w1_s ; [15768,15808) b1_s ; [15808,15848) c2s ; [15848,15912) red_s
#define K1_SMEM_FLOATS 15912

#define MMA_TILE(Ap, CB, NTLO, NTHI) do {                                     \
    uint32_t a0 = __float_as_uint((Ap)[tg152]);                               \
    uint32_t a1 = __float_as_uint((Ap)[tg152 + 8]);                           \
    uint32_t a2 = __float_as_uint((Ap)[tg152 + 608]);                         \
    uint32_t a3 = __float_as_uint((Ap)[tg152 + 616]);                         \
    _Pragma("unroll")                                                         \
    for (int nt = (NTLO); nt < (NTHI); ++nt) {                                \
        float* c = C[(CB) + nt - (NTLO)];                                     \
        asm("mma.sync.aligned.m16n8k8.row.col.f32.tf32.tf32.f32 "             \
            "{%0,%1,%2,%3}, {%4,%5,%6,%7}, {%8,%9}, {%0,%1,%2,%3};"           \
            : "+f"(c[0]), "+f"(c[1]), "+f"(c[2]), "+f"(c[3])                  \
            : "r"(a0), "r"(a1), "r"(a2), "r"(a3), "r"(B0[nt]), "r"(B1[nt]));  \
    }                                                                         \
} while (0)

#define KSTEPS(MT0, L0, H0, C0, MT1, L1, H1, C1, MT2, L2, H2, C2) do {        \
    _Pragma("unroll")                                                         \
    for (int s = 0; s < 5; ++s) {                                             \
        const float* wk = wb + (8 * s + tg) * 40 + g2;                        \
        uint32_t B0[5], B1[5];                                                \
        _Pragma("unroll")                                                     \
        for (int nt = 0; nt < 5; ++nt) {                                      \
            B0[nt] = __float_as_uint(wk[8 * nt]);                             \
            B1[nt] = __float_as_uint(wk[160 + 8 * nt]);                       \
        }                                                                     \
        const float* As = Db + s * 1216 + g2;                                 \
        MMA_TILE(As + 16 * (MT0), C0, L0, H0);                                \
        MMA_TILE(As + 16 * (MT1), C1, L1, H1);                                \
        MMA_TILE(As + 16 * (MT2), C2, L2, H2);                                \
    }                                                                         \
} while (0)

#define EPI_TILE(MT, NTLO, NTHI, CB) do {                                     \
    _Pragma("unroll")                                                         \
    for (int nt = (NTLO); nt < (NTHI); ++nt) {                                \
        float* c = C[(CB) + nt - (NTLO)];                                     \
        int px0 = 16 * (MT) + g2;                                             \
        int co = 8 * nt + 2 * tg;                                             \
        *(float2*)(act2 + px0 * 40 + co) =                                    \
            make_float2(frelu(c2s[co] + c[0]), frelu(c2s[co + 1] + c[1]));    \
        *(float2*)(act2 + (px0 + 8) * 40 + co) =                              \
            make_float2(frelu(c2s[co] + c[2]), frelu(c2s[co + 1] + c[3]));    \
    }                                                                         \
} while (0)

__global__ void __launch_bounds__(256, 3) patch_kernel(
    const float* __restrict__ img, const float* __restrict__ lab,
    const float* __restrict__ msk,
    const float* __restrict__ w1, const float* __restrict__ b1,
    const float* __restrict__ d1b)
{
    extern __shared__ float smem[];
    float* w2b   = smem;
    float* w1_s  = smem + 15408;
    float* b1_s  = smem + 15768;
    float* c2s   = smem + 15808;
    float* red_s = smem + 15848;

    const int t  = threadIdx.x;
    const int wg = t >> 7;            // patch group 0/1
    const int wt = t & 127;           // thread within group
    float* tok_s = smem + 1600 + wg * 348;
    float* Dg    = smem + 3216 + wg * 6096;

    const int n = 2 * blockIdx.x + wg;
    const int g = n >> 10;
    const int ij = n & 1023;
    const int i = ij >> 5, j = ij & 31;
    const int sx = g & 1, sy = g >> 1;
    const int r0 = 16 * i + 8 * sx - 4;
    const int c0 = 16 * j + 8 * sy - 4;
    const float cid = (float)((2 * i + sx) * 64 + (2 * j + sy));

    const uint32_t w2b_u = smem_u32(w2b);

    // prefetch conv2 tap-0 tf32 weights into stage 0 (256 threads)
    #pragma unroll
    for (int r = 0; r < 2; ++r) {
        int k = t + 256 * r;
        if (k < 400) cp_async16(w2b_u + k * 16, (const float4*)g_w2t + k);
    }
    CP_COMMIT();

    for (int k = t; k < 360; k += 256) w1_s[k] = w1[k];
    if (t < 40) { b1_s[t] = b1[t]; c2s[t] = g_c2[t]; }
    if (wt < 128) for (int k = wt; k < 324; k += 128) tok_s[k] = 0.f;
    // zero D regions + guards: floats [3200, 15408) = 12208 = 3052 float4
    {
        float4* z = (float4*)(smem + 3200);
        #pragma unroll
        for (int r = 0; r < 12; ++r) {
            int k = t + 256 * r;
            if (k < 3052) z[k] = make_float4(0.f, 0.f, 0.f, 0.f);
        }
    }
    __syncthreads();

    // tokens + label sums (per group, 128 threads)
    float sum_f = 0.f, sum_lp = 0.f;
    #pragma unroll
    for (int pp = 0; pp < 2; ++pp) {
        int p = wt + 128 * pp;
        int py = p >> 4, px = p & 15;
        int gr = r0 + py, gc = c0 + px;
        bool inb = (gr >= 0 && gr < 512 && gc >= 0 && gc < 512);
        float m = inb ? msk[gr * 512 + gc] : -1.f;
        float f = (m == cid) ? 1.f : 0.f;
        float iv = (inb ? img[gr * 512 + gc] : 0.f) * f;
        float lv = (inb ? lab[gr * 512 + gc] : 0.f) * f;
        tok_s[(py + 1) * 18 + px + 1] = iv;
        sum_f += f; sum_lp += lv;
    }
    #pragma unroll
    for (int o = 16; o; o >>= 1) {
        sum_f  += __shfl_down_sync(0xffffffffu, sum_f, o);
        sum_lp += __shfl_down_sync(0xffffffffu, sum_lp, o);
    }
    if ((wt & 31) == 0) {
        red_s[wg * 8 + (wt >> 5) * 2] = sum_f;
        red_s[wg * 8 + (wt >> 5) * 2 + 1] = sum_lp;
    }
    __syncthreads();
    if (wt == 0) {
        float sf = red_s[wg * 8] + red_s[wg * 8 + 2] + red_s[wg * 8 + 4] + red_s[wg * 8 + 6];
        float sl = red_s[wg * 8 + 1] + red_s[wg * 8 + 3] + red_s[wg * 8 + 5] + red_s[wg * 8 + 7];
        g_label[n] = dround(dround(sl / (sf + 1e-8f)));
    }

    // ---- conv1 delta on 10x10 -> 12x12 zero-ringed planes (stride 152), tf32 ----
    if (wt < 100) {
        int rr = 3 + wt / 10, cc = 3 + wt - 10 * (wt / 10);
        float t9[9];
        #pragma unroll
        for (int k = 0; k < 9; k++) t9[k] = tok_s[(rr + k / 3) * 18 + (cc + k % 3)];
        int dpos = (rr - 2) * 12 + (cc - 2);
        #pragma unroll 8
        for (int c = 0; c < 40; c++) {
            float s = 0.f;
            #pragma unroll
            for (int k = 0; k < 9; k++) s = fmaf(t9[k], w1_s[k * 40 + c], s);
            float b = b1_s[c];
            Dg[c * 152 + dpos] = to_tf32(frelu(b + s) - frelu(b));
        }
    }

    // ---- conv2 delta via tf32 mma ----
    const int w4 = (t >> 5) & 3, l = t & 31;
    const int g2 = l >> 2, tg = l & 3;
    const int tg152 = tg * 152;

    float C[12][4];
    #pragma unroll
    for (int a = 0; a < 12; a++)
        #pragma unroll
        for (int b = 0; b < 4; b++) C[a][b] = 0.f;

    for (int tap = 0; tap < 9; ++tap) {
        __syncthreads();
        if (tap < 8) {
            uint32_t dst = w2b_u + ((tap + 1) & 1) * 6400;
            const float4* src = (const float4*)(g_w2t + (tap + 1) * 1600);
            #pragma unroll
            for (int r = 0; r < 2; ++r) {
                int k = t + 256 * r;
                if (k < 400) cp_async16(dst + k * 16, src + k);
            }
            CP_COMMIT();
            CP_WAIT(1);
        } else {
            CP_WAIT(0);
        }
        __syncthreads();

        const int off = (tap / 3 - 1) * 12 + (tap % 3) - 1;
        const float* wb = w2b + (tap & 1) * 1600;
        const float* Db = Dg + off;

        if (w4 == 0) {
            KSTEPS(0, 0, 5, 0,   1, 0, 5, 5,   2, 0, 2, 10);
        } else if (w4 == 1) {
            KSTEPS(2, 2, 5, 0,   3, 0, 5, 3,   4, 0, 3, 8);
        } else if (w4 == 2) {
            KSTEPS(4, 3, 5, 0,   5, 0, 5, 2,   6, 0, 4, 7);
        } else {
            KSTEPS(6, 4, 5, 0,   7, 0, 5, 1,   8, 0, 5, 6);
        }
    }
    __syncthreads();

    // epilogue: act2 = relu(c2 + delta)
    float* act2 = Dg;
    if (w4 == 0) {
        EPI_TILE(0, 0, 5, 0); EPI_TILE(1, 0, 5, 5); EPI_TILE(2, 0, 2, 10);
    } else if (w4 == 1) {
        EPI_TILE(2, 2, 5, 0); EPI_TILE(3, 0, 5, 3); EPI_TILE(4, 0, 3, 8);
    } else if (w4 == 2) {
        EPI_TILE(4, 3, 5, 0); EPI_TILE(5, 0, 5, 2); EPI_TILE(6, 0, 4, 7);
    } else {
        EPI_TILE(6, 4, 5, 0); EPI_TILE(7, 0, 5, 1); EPI_TILE(8, 0, 5, 6);
    }
    __syncthreads();

    // ---- dense1 interior (per group) ----
    const unsigned long long* wtp = (const unsigned long long*)g_wint;
    unsigned long long p3[3] = {0ull, 0ull, 0ull};
    for (int m = 0; m < 45; ++m) {
        int f = wt + 128 * m;
        float v = act2[f];
        unsigned long long a2;
        asm("mov.b64 %0, {%1, %2};" : "=l"(a2) : "f"(v), "f"(v));
        #pragma unroll
        for (int k2 = 0; k2 < 3; k2++) {
            unsigned long long wv = __ldg(wtp + k2 * 5760 + f);
            asm("fma.rn.f32x2 %0, %1, %2, %0;" : "+l"(p3[k2]) : "l"(a2), "l"(wv));
        }
    }
    float part[6];
    #pragma unroll
    for (int k2 = 0; k2 < 3; k2++)
        asm("mov.b64 {%0, %1}, %2;" : "=f"(part[2 * k2]), "=f"(part[2 * k2 + 1]) : "l"(p3[k2]));
    #pragma unroll
    for (int k = 0; k < 6; k++)
        #pragma unroll
        for (int o = 16; o; o >>= 1) part[k] += __shfl_down_sync(0xffffffffu, part[k], o);
    __syncthreads();   // red_s label-phase reads complete
    if (l == 0) {
        #pragma unroll
        for (int k = 0; k < 6; k++) red_s[wg * 24 + (w4 >> 0) * 6 + k] = part[k];
    }
    __syncthreads();
    if (wt < 6) {
        const float* rb = red_s + wg * 24;
        float s = rb[wt] + rb[6 + wt] + rb[12 + wt] + rb[18 + wt];
        g_nodes[n * 6 + wt] = frelu(s + g_extk[wt] + d1b[wt]);
    }
}

// ---------------- kernel 2: edge MLP + deterministic bucketing ----------------
__global__ void __launch_bounds__(128) edge_kernel(
    const int* __restrict__ snd, const int* __restrict__ rcv, int E,
    const float* __restrict__ we0, const float* __restrict__ be0,
    const float* __restrict__ we1, const float* __restrict__ be1,
    const float* __restrict__ we2, const float* __restrict__ be2,
    const float* __restrict__ we3, const float* __restrict__ be3)
{
    int e = blockIdx.x * 128 + threadIdx.x;
    if (e >= E) return;
    int s = snd[e], r = rcv[e];
    float x[13];
    #pragma unroll
    for (int k = 0; k < 6; k++) { x[k] = g_nodes[s * 6 + k]; x[6 + k] = g_nodes[r * 6 + k]; }
    x[12] = 1.f;

    float h0[5], h1[5], h2[5];
    #pragma unroll
    for (int k = 0; k < 5; k++) {
        float a = __ldg(be0 + k);
        #pragma unroll
        for (int i2 = 0; i2 < 13; i2++) a = fmaf(x[i2], __ldg(we0 + i2 * 5 + k), a);
        h0[k] = frelu(a);
    }
    #pragma unroll
    for (int k = 0; k < 5; k++) {
        float a = __ldg(be1 + k);
        #pragma unroll
        for (int i2 = 0; i2 < 5; i2++) a = fmaf(h0[i2], __ldg(we1 + i2 * 5 + k), a);
        h1[k] = frelu(a);
    }
    #pragma unroll
    for (int k = 0; k < 5; k++) {
        float a = __ldg(be2 + k);
        #pragma unroll
        for (int i2 = 0; i2 < 5; i2++) a = fmaf(h1[i2], __ldg(we2 + i2 * 5 + k), a);
        h2[k] = frelu(a);
    }
    float o[10];
    #pragma unroll
    for (int k = 0; k < 10; k++) {
        float a = __ldg(be3 + k);
        #pragma unroll
        for (int i2 = 0; i2 < 5; i2++) a = fmaf(h2[i2], __ldg(we3 + i2 * 10 + k), a);
        o[k] = a;
    }
    float* eb = g_efeat + e * 12;
    *(float4*)(eb + 0) = make_float4(o[0], o[1], o[2], o[3]);
    *(float4*)(eb + 4) = make_float4(o[4], o[5], o[6], o[7]);
    *(float2*)(eb + 8) = make_float2(o[8], o[9]);
    int pos = atomicAdd(&g_cnt[r], 1);
    if (pos < 16) g_slot[r * 16 + pos] = e;
}

// ---------------- kernel 3: 4 lanes/node agg + node MLP + CE loss ----------------
__global__ void __launch_bounds__(128) node_kernel(
    const float* __restrict__ wn0, const float* __restrict__ bn0,
    const float* __restrict__ wn1, const float* __restrict__ bn1,
    const float* __restrict__ wn2, const float* __restrict__ bn2,
    const float* __restrict__ wn3, const float* __restrict__ bn3,
    const float* __restrict__ wout, const float* __restrict__ bout,
    float* __restrict__ out)
{
    int t = threadIdx.x;
    int n = blockIdx.x * 32 + (t >> 2);
    int q = t & 3;

    int d = g_cnt[n]; if (d > 16) d = 16;
    int ids[16];
    for (int a = 0; a < d; a++) ids[a] = g_slot[n * 16 + a];
    for (int a = 1; a < d; a++) {
        int key = ids[a]; int b = a - 1;
        while (b >= 0 && ids[b] > key) { ids[b + 1] = ids[b]; b--; }
        ids[b + 1] = key;
    }
    float agg[10];
    #pragma unroll
    for (int k = 0; k < 10; k++) agg[k] = 0.f;
    for (int a = q; a < d; a += 4) {
        const float* eb = g_efeat + ids[a] * 12;
        float4 v0 = *(const float4*)(eb + 0);
        float4 v1 = *(const float4*)(eb + 4);
        float2 v2 = *(const float2*)(eb + 8);
        agg[0] += v0.x; agg[1] += v0.y; agg[2] += v0.z; agg[3] += v0.w;
        agg[4] += v1.x; agg[5] += v1.y; agg[6] += v1.z; agg[7] += v1.w;
        agg[8] += v2.x; agg[9] += v2.y;
    }
    #pragma unroll
    for (int k = 0; k < 10; k++) {
        agg[k] += __shfl_xor_sync(0xffffffffu, agg[k], 1);
        agg[k] += __shfl_xor_sync(0xffffffffu, agg[k], 2);
    }
    if (q != 0) return;

    float x[17];
    #pragma unroll
    for (int k = 0; k < 6; k++) x[k] = g_nodes[n * 6 + k];
    #pragma unroll
    for (int k = 0; k < 10; k++) x[6 + k] = agg[k];
    x[16] = 1.f;

    float h0[5], h1[5], h2[5], o[10];
    #pragma unroll
    for (int k = 0; k < 5; k++) {
        float a = __ldg(bn0 + k);
        #pragma unroll
        for (int i2 = 0; i2 < 17; i2++) a = fmaf(x[i2], __ldg(wn0 + i2 * 5 + k), a);
        h0[k] = frelu(a);
    }
    #pragma unroll
    for (int k = 0; k < 5; k++) {
        float a = __ldg(bn1 + k);
        #pragma unroll
        for (int i2 = 0; i2 < 5; i2++) a = fmaf(h0[i2], __ldg(wn1 + i2 * 5 + k), a);
        h1[k] = frelu(a);
    }
    #pragma unroll
    for (int k = 0; k < 5; k++) {
        float a = __ldg(bn2 + k);
        #pragma unroll
        for (int i2 = 0; i2 < 5; i2++) a = fmaf(h1[i2], __ldg(wn2 + i2 * 5 + k), a);
        h2[k] = frelu(a);
    }
    #pragma unroll
    for (int k = 0; k < 10; k++) {
        float a = __ldg(bn3 + k);
        #pragma unroll
        for (int i2 = 0; i2 < 5; i2++) a = fmaf(h2[i2], __ldg(wn3 + i2 * 10 + k), a);
        o[k] = a;
    }
    float l0 = __ldg(bout + 0), l1 = __ldg(bout + 1);
    #pragma unroll
    for (int i2 = 0; i2 < 10; i2++) {
        l0 = fmaf(o[i2], __ldg(wout + i2 * 2 + 0), l0);
        l1 = fmaf(o[i2], __ldg(wout + i2 * 2 + 1), l1);
    }
    float m = fmaxf(l0, l1);
    float lse = m + logf(expf(l0 - m) + expf(l1 - m));
    float sv = g_label[n];
    out[n] = -((1.f - sv) * (l0 - lse) + sv * (l1 - lse));
}

// ---------------- launch ----------------
extern "C" void kernel_launch(void* const* d_in, const int* in_sizes, int n_in,
                              void* d_out, int out_size)
{
    const float* img = (const float*)d_in[0];
    const float* lab = (const float*)d_in[1];
    const float* msk = (const float*)d_in[2];
    const float* w1  = (const float*)d_in[3];
    const float* b1  = (const float*)d_in[4];
    const float* w2  = (const float*)d_in[5];
    const float* b2  = (const float*)d_in[6];
    const float* d1w = (const float*)d_in[7];
    const float* d1b = (const float*)d_in[8];
    const float* we0 = (const float*)d_in[9];
    const float* be0 = (const float*)d_in[10];
    const float* we1 = (const float*)d_in[11];
    const float* be1 = (const float*)d_in[12];
    const float* we2 = (const float*)d_in[13];
    const float* be2 = (const float*)d_in[14];
    const float* we3 = (const float*)d_in[15];
    const float* be3 = (const float*)d_in[16];
    const float* wn0 = (const float*)d_in[17];
    const float* bn0 = (const float*)d_in[18];
    const float* wn1 = (const float*)d_in[19];
    const float* bn1 = (const float*)d_in[20];
    const float* wn2 = (const float*)d_in[21];
    const float* bn2 = (const float*)d_in[22];
    const float* wn3 = (const float*)d_in[23];
    const float* bn3 = (const float*)d_in[24];
    const float* wout = (const float*)d_in[25];
    const float* bout = (const float*)d_in[26];
    const int* snd = (const int*)d_in[27];
    const int* rcv = (const int*)d_in[28];
    int E = in_sizes[27];

    int smem_bytes = K1_SMEM_FLOATS * (int)sizeof(float);
    static int configured = -1;
    if (configured != smem_bytes) {
        cudaFuncSetAttribute(patch_kernel, cudaFuncAttributeMaxDynamicSharedMemorySize, smem_bytes);
        configured = smem_bytes;
    }

    pre_kernel<<<191, 128>>>(b1, w2, b2, d1w);
    patch_kernel<<<2048, 256, smem_bytes>>>(img, lab, msk, w1, b1, d1b);
    edge_kernel<<<(E + 127) / 128, 128>>>(snd, rcv, E, we0, be0, we1, be1, we2, be2, we3, be3);
    node_kernel<<<128, 128>>>(wn0, bn0, wn1, bn1, wn2, bn2, wn3, bn3, wout, bout, (float*)d_out);

    (void)n_in; (void)out_size;
}